// round 1
// baseline (speedup 1.0000x reference)
#include <cuda_runtime.h>

// Problem constants
#define NPART   148      // grid size for K1/K3 (one CTA per SM)
#define NCHUNK  4096     // total chunks of 64 points (262144 / 64)
// chunk -> batch: b = chunk >> 10   (1024 chunks of 64 pts = 65536 pts per batch)

// Deterministic scratch (no cudaMalloc allowed)
__device__ float g_part[4 * NPART * 4096];   // per-CTA partial kv  [b][cta][h*1024+d*32+e]
__device__ float g_kv[4 * 4096];             // reduced kv          [b][h*1024+d*32+e]
__device__ float g_wqeff[4 * 16384];         // folded weights      [b][c'*128 + (e*4+h)]

// ---- packed f32x2 helpers (FFMA2 is only reachable via PTX fma.rn.f32x2) ----
__device__ __forceinline__ unsigned long long dup2(float x) {
    unsigned long long r;
    asm("mov.b64 %0, {%1, %1};" : "=l"(r) : "f"(x));
    return r;
}
__device__ __forceinline__ unsigned long long fma2(unsigned long long a,
                                                   unsigned long long b,
                                                   unsigned long long c) {
    unsigned long long d;
    asm("fma.rn.f32x2 %0, %1, %2, %3;" : "=l"(d) : "l"(a), "l"(b), "l"(c));
    return d;
}
__device__ __forceinline__ float2 unpk(unsigned long long a) {
    float2 f;
    asm("mov.b64 {%0, %1}, %2;" : "=f"(f.x), "=f"(f.y) : "l"(a));
    return f;
}

// ============================================================================
// Kernel 1: fused (X@Wk, X@Wv) -> LayerNorm -> per-head outer-product partials
// 256 threads, 148 persistent CTAs. smem: Wk|Wv (32768 f) + 64-pt buffer (16384 f)
// ============================================================================
__global__ void __launch_bounds__(256, 1)
k1_kv(const float* __restrict__ X,
      const float* __restrict__ Wk, const float* __restrict__ Wv,
      const float* __restrict__ gamma, const float* __restrict__ beta)
{
    extern __shared__ float sm[];
    float* sW   = sm;            // [0:16384) Wk[c'][ch], [16384:32768) Wv[c'][ch]
    float* sBuf = sm + 32768;    // matvec phase: X[64][128]; LN phase: kn/vn [64][256]

    const int tid  = threadIdx.x;
    const int lane = tid & 31;
    const int warp = tid >> 5;   // 8 warps; warp handles 8 local points

    // Load Wk, Wv into shared (vectorized)
    {
        float4* d4 = (float4*)sW;
        const float4* k4 = (const float4*)Wk;
        const float4* v4 = (const float4*)Wv;
        for (int i = tid; i < 4096; i += 256) {
            d4[i] = k4[i];
            d4[4096 + i] = v4[i];
        }
    }
    // gamma/beta for this lane's 4 channels (channel = 4*lane .. 4*lane+3)
    const float4 g4  = ((const float4*)gamma)[lane];
    const float4 be4 = ((const float4*)beta)[lane];

    // Outer-product entry assignment: 4096 entries / 256 threads = 16 (4d x 4e)
    const int hh = tid >> 6;              // head 0..3
    const int idx = tid & 63;
    const int d0 = (idx >> 3) << 2;       // 0,4,...,28
    const int e0 = (idx & 7) << 2;        // 0,4,...,28

    unsigned long long acc[4][2];         // [d][e-pair]: (e0,e0+1),(e0+2,e0+3)
#pragma unroll
    for (int i = 0; i < 4; i++) { acc[i][0] = 0ull; acc[i][1] = 0ull; }

    int cur_b = -1;
    __syncthreads();

    for (int chunk = blockIdx.x; chunk < NCHUNK; chunk += NPART) {
        const int b = chunk >> 10;
        if (b != cur_b) {
            if (cur_b >= 0) {
                // flush partial kv for previous batch (plain stores: deterministic)
                float* dst = g_part + ((size_t)cur_b * NPART + blockIdx.x) * 4096
                           + hh * 1024 + d0 * 32 + e0;
#pragma unroll
                for (int i = 0; i < 4; i++) {
                    float2 lo = unpk(acc[i][0]);
                    float2 hi = unpk(acc[i][1]);
                    *(float4*)(dst + i * 32) = make_float4(lo.x, lo.y, hi.x, hi.y);
                    acc[i][0] = 0ull; acc[i][1] = 0ull;
                }
            }
            cur_b = b;
        }

        __syncthreads();   // protect sBuf from previous iteration's readers

        // ---- Phase 0: stage 64 points of X ----
        {
            const float4* src = (const float4*)X + (size_t)chunk * 2048;
            float4* dst = (float4*)sBuf;
            for (int i = tid; i < 2048; i += 256) dst[i] = src[i];
        }
        __syncthreads();

        // ---- Phase 1: matvec k = X@Wk, v = X@Wv (f32x2, 8 pts/warp, 4 ch/lane) ----
        unsigned long long ka[8][2], va[8][2];
#pragma unroll
        for (int p = 0; p < 8; p++) {
            ka[p][0] = ka[p][1] = 0ull;
            va[p][0] = va[p][1] = 0ull;
        }
        const float* wk = sW + 4 * lane;
        const float* wv = sW + 16384 + 4 * lane;
        const float* xb = sBuf + (warp << 3) * 128;
#pragma unroll 4
        for (int c = 0; c < 128; c += 2) {
            ulonglong2 wk0 = *(const ulonglong2*)(wk + c * 128);
            ulonglong2 wk1 = *(const ulonglong2*)(wk + c * 128 + 128);
            ulonglong2 wv0 = *(const ulonglong2*)(wv + c * 128);
            ulonglong2 wv1 = *(const ulonglong2*)(wv + c * 128 + 128);
#pragma unroll
            for (int p = 0; p < 8; p++) {
                float2 x2 = *(const float2*)(xb + p * 128 + c);
                unsigned long long x0 = dup2(x2.x);
                unsigned long long x1 = dup2(x2.y);
                ka[p][0] = fma2(wk0.x, x0, ka[p][0]);
                ka[p][1] = fma2(wk0.y, x0, ka[p][1]);
                va[p][0] = fma2(wv0.x, x0, va[p][0]);
                va[p][1] = fma2(wv0.y, x0, va[p][1]);
                ka[p][0] = fma2(wk1.x, x1, ka[p][0]);
                ka[p][1] = fma2(wk1.y, x1, ka[p][1]);
                va[p][0] = fma2(wv1.x, x1, va[p][0]);
                va[p][1] = fma2(wv1.y, x1, va[p][1]);
            }
        }
        __syncthreads();   // all X reads done; sBuf becomes kn/vn storage

        // ---- Phase 2: LayerNorm over 128 channels (warp reduction), store kn/vn ----
#pragma unroll
        for (int p = 0; p < 8; p++) {
            float2 a0 = unpk(ka[p][0]), a1 = unpk(ka[p][1]);
            float2 b0 = unpk(va[p][0]), b1 = unpk(va[p][1]);
            float sk = a0.x + a0.y + a1.x + a1.y;
            float qk = a0.x * a0.x + a0.y * a0.y + a1.x * a1.x + a1.y * a1.y;
            float sv = b0.x + b0.y + b1.x + b1.y;
            float qv = b0.x * b0.x + b0.y * b0.y + b1.x * b1.x + b1.y * b1.y;
#pragma unroll
            for (int off = 16; off; off >>= 1) {
                sk += __shfl_xor_sync(0xffffffffu, sk, off);
                qk += __shfl_xor_sync(0xffffffffu, qk, off);
                sv += __shfl_xor_sync(0xffffffffu, sv, off);
                qv += __shfl_xor_sync(0xffffffffu, qv, off);
            }
            const float muk = sk * (1.f / 128.f);
            const float rk  = rsqrtf(qk * (1.f / 128.f) - muk * muk + 1e-5f);
            const float muv = sv * (1.f / 128.f);
            const float rv  = rsqrtf(qv * (1.f / 128.f) - muv * muv + 1e-5f);
            float* row = sBuf + (((warp << 3) + p) << 8) + 4 * lane;  // [pt][256]
            *(float4*)row = make_float4((a0.x - muk) * rk * g4.x + be4.x,
                                        (a0.y - muk) * rk * g4.y + be4.y,
                                        (a1.x - muk) * rk * g4.z + be4.z,
                                        (a1.y - muk) * rk * g4.w + be4.w);
            *(float4*)(row + 128) = make_float4((b0.x - muv) * rv * g4.x + be4.x,
                                                (b0.y - muv) * rv * g4.y + be4.y,
                                                (b1.x - muv) * rv * g4.z + be4.z,
                                                (b1.y - muv) * rv * g4.w + be4.w);
        }
        __syncthreads();

        // ---- Phase 3: accumulate kv[h][d][e] += kn[h*32+d] * vn[h*32+e] ----
        const float* kb = sBuf + hh * 32 + d0;
        const float* vb = sBuf + 128 + hh * 32 + e0;
#pragma unroll 8
        for (int p = 0; p < 64; p++) {
            float4 kk = *(const float4*)(kb + p * 256);
            ulonglong2 vv = *(const ulonglong2*)(vb + p * 256);
            unsigned long long k0 = dup2(kk.x), k1 = dup2(kk.y);
            unsigned long long k2 = dup2(kk.z), k3 = dup2(kk.w);
            acc[0][0] = fma2(vv.x, k0, acc[0][0]); acc[0][1] = fma2(vv.y, k0, acc[0][1]);
            acc[1][0] = fma2(vv.x, k1, acc[1][0]); acc[1][1] = fma2(vv.y, k1, acc[1][1]);
            acc[2][0] = fma2(vv.x, k2, acc[2][0]); acc[2][1] = fma2(vv.y, k2, acc[2][1]);
            acc[3][0] = fma2(vv.x, k3, acc[3][0]); acc[3][1] = fma2(vv.y, k3, acc[3][1]);
        }
    }

    // final flush (last batch seen; every CTA visits every batch at grid=148)
    if (cur_b >= 0) {
        float* dst = g_part + ((size_t)cur_b * NPART + blockIdx.x) * 4096
                   + hh * 1024 + d0 * 32 + e0;
#pragma unroll
        for (int i = 0; i < 4; i++) {
            float2 lo = unpk(acc[i][0]);
            float2 hi = unpk(acc[i][1]);
            *(float4*)(dst + i * 32) = make_float4(lo.x, lo.y, hi.x, hi.y);
        }
    }
}

// ============================================================================
// Kernel 2a: reduce 148 per-CTA partials -> g_kv.  grid 64 x 256 = 16384 thr
// ============================================================================
__global__ void k2a_reduce()
{
    const int gid = blockIdx.x * 256 + threadIdx.x;   // 0..16383 = [b][entry]
    const int b = gid >> 12;
    const int e = gid & 4095;
    const float* src = g_part + (size_t)b * NPART * 4096 + e;
    float s = 0.f;
#pragma unroll 4
    for (int j = 0; j < NPART; j++) s += src[(size_t)j * 4096];
    g_kv[gid] = s;
}

// ============================================================================
// Kernel 2b: Wq_eff[b][c'][e*4+h] = (1/N) * sum_d Wq[c'][h*32+d] * kv[b][h][d][e]
// grid 256 x 256 = 65536 outputs
// ============================================================================
__global__ void k2b_fold(const float* __restrict__ Wq)
{
    const int gid = blockIdx.x * 256 + threadIdx.x;   // 0..65535
    const int b  = gid >> 14;
    const int r  = gid & 16383;
    const int cp = r >> 7;
    const int co = r & 127;
    const int e  = co >> 2;
    const int h  = co & 3;
    const float* wq = Wq + cp * 128 + h * 32;
    const float* kv = g_kv + b * 4096 + h * 1024 + e;
    float s = 0.f;
#pragma unroll
    for (int d = 0; d < 32; d++) s += wq[d] * kv[d * 32];
    g_wqeff[b * 16384 + cp * 128 + co] = s * (1.f / 65536.f);
}

// ============================================================================
// Kernel 3: out[p][:] = X[p][:] @ Wq_eff[b]   (folded q-projection + attention)
// 256 threads, 148 persistent CTAs. smem: Wq_eff (16384 f) + X chunk (8192 f)
// ============================================================================
__global__ void __launch_bounds__(256, 1)
k3_out(const float* __restrict__ X, float* __restrict__ out)
{
    extern __shared__ float sm[];
    float* sW = sm;            // 16384 floats
    float* sX = sm + 16384;    // 8192 floats (64 pts x 128)

    const int tid  = threadIdx.x;
    const int lane = tid & 31;
    const int warp = tid >> 5;

    int cur_b = -1;
    for (int chunk = blockIdx.x; chunk < NCHUNK; chunk += NPART) {
        const int b = chunk >> 10;
        __syncthreads();
        if (b != cur_b) {
            float4* d4 = (float4*)sW;
            const float4* s4 = (const float4*)g_wqeff + b * 4096;
            for (int i = tid; i < 4096; i += 256) d4[i] = s4[i];
            cur_b = b;
        }
        {
            const float4* src = (const float4*)X + (size_t)chunk * 2048;
            float4* dst = (float4*)sX;
            for (int i = tid; i < 2048; i += 256) dst[i] = src[i];
        }
        __syncthreads();

        unsigned long long a[8][2];
#pragma unroll
        for (int p = 0; p < 8; p++) { a[p][0] = 0ull; a[p][1] = 0ull; }
        const float* w  = sW + 4 * lane;
        const float* xb = sX + (warp << 3) * 128;
#pragma unroll 4
        for (int c = 0; c < 128; c += 2) {
            ulonglong2 w0 = *(const ulonglong2*)(w + c * 128);
            ulonglong2 w1 = *(const ulonglong2*)(w + c * 128 + 128);
#pragma unroll
            for (int p = 0; p < 8; p++) {
                float2 x2 = *(const float2*)(xb + p * 128 + c);
                unsigned long long x0 = dup2(x2.x);
                unsigned long long x1 = dup2(x2.y);
                a[p][0] = fma2(w0.x, x0, a[p][0]);
                a[p][1] = fma2(w0.y, x0, a[p][1]);
                a[p][0] = fma2(w1.x, x1, a[p][0]);
                a[p][1] = fma2(w1.y, x1, a[p][1]);
            }
        }
        float4* o4 = (float4*)out + (size_t)chunk * 2048;
#pragma unroll
        for (int p = 0; p < 8; p++) {
            float2 lo = unpk(a[p][0]);
            float2 hi = unpk(a[p][1]);
            o4[((warp << 3) + p) * 32 + lane] = make_float4(lo.x, lo.y, hi.x, hi.y);
        }
    }
}

// ============================================================================
extern "C" void kernel_launch(void* const* d_in, const int* in_sizes, int n_in,
                              void* d_out, int out_size)
{
    (void)in_sizes; (void)n_in; (void)out_size;
    const float* X     = (const float*)d_in[0];
    const float* Wq    = (const float*)d_in[1];
    const float* Wk    = (const float*)d_in[2];
    const float* Wv    = (const float*)d_in[3];
    const float* gamma = (const float*)d_in[4];
    const float* beta  = (const float*)d_in[5];
    float* out = (float*)d_out;

    cudaFuncSetAttribute(k1_kv, cudaFuncAttributeMaxDynamicSharedMemorySize,
                         49152 * (int)sizeof(float));   // 192 KB
    cudaFuncSetAttribute(k3_out, cudaFuncAttributeMaxDynamicSharedMemorySize,
                         24576 * (int)sizeof(float));   // 96 KB

    k1_kv<<<NPART, 256, 49152 * sizeof(float)>>>(X, Wk, Wv, gamma, beta);
    k2a_reduce<<<64, 256>>>();
    k2b_fold<<<256, 256>>>(Wq);
    k3_out<<<NPART, 256, 24576 * sizeof(float)>>>(X, out);
}

// round 2
// speedup vs baseline: 1.0749x; 1.0749x over previous
#include <cuda_runtime.h>

// Problem constants
#define NPART    148     // persistent CTAs (one per SM)
#define NCHUNK1  4096    // K1: chunks of 64 points   (262144/64);  b = chunk>>10
#define NCHUNK3  2048    // K3: chunks of 128 points  (262144/128); b = chunk>>9

// Deterministic scratch (no cudaMalloc allowed)
__device__ float g_part[4 * NPART * 4096];   // per-CTA partial kv  [b][cta][h*1024+d*32+e]
__device__ float g_kv[4 * 4096];             // reduced kv          [b][h*1024+d*32+e]
__device__ float g_wqeff[4 * 16384];         // folded weights      [b][c'*128 + (e*4+h)]

// ---- packed f32x2 helpers (FFMA2 is only reachable via PTX fma.rn.f32x2) ----
__device__ __forceinline__ unsigned long long dup2(float x) {
    unsigned long long r;
    asm("mov.b64 %0, {%1, %1};" : "=l"(r) : "f"(x));
    return r;
}
__device__ __forceinline__ unsigned long long fma2(unsigned long long a,
                                                   unsigned long long b,
                                                   unsigned long long c) {
    unsigned long long d;
    asm("fma.rn.f32x2 %0, %1, %2, %3;" : "=l"(d) : "l"(a), "l"(b), "l"(c));
    return d;
}
__device__ __forceinline__ float2 unpk(unsigned long long a) {
    float2 f;
    asm("mov.b64 {%0, %1}, %2;" : "=f"(f.x), "=f"(f.y) : "l"(a));
    return f;
}

// ---- cp.async helpers ----
__device__ __forceinline__ void cp16(float* smem_dst, const float* gsrc) {
    unsigned s = (unsigned)__cvta_generic_to_shared(smem_dst);
    asm volatile("cp.async.cg.shared.global [%0], [%1], 16;" :: "r"(s), "l"(gsrc));
}
__device__ __forceinline__ void cp_commit() {
    asm volatile("cp.async.commit_group;");
}
__device__ __forceinline__ void cp_wait_all() {
    asm volatile("cp.async.wait_group 0;");
}

// ============================================================================
// Kernel 1: fused (X@Wk, X@Wv) -> LayerNorm -> per-head outer-product partials
// 256 threads, 148 persistent CTAs.
// smem (floats): sW [0,32768) = Wk|Wv ; sX [32768,40960) ; sLN [40960,57344)
// Total 229376 bytes. X staging is cp.async-pipelined against phases 2/3.
// ============================================================================
__global__ void __launch_bounds__(256, 1)
k1_kv(const float* __restrict__ X,
      const float* __restrict__ Wk, const float* __restrict__ Wv,
      const float* __restrict__ gamma, const float* __restrict__ beta)
{
    extern __shared__ float sm[];
    float* sW  = sm;            // 32768 floats
    float* sX  = sm + 32768;    // 8192 floats : 64 pts x 128
    float* sLN = sm + 40960;    // 16384 floats: kn/vn [64][256]

    const int tid  = threadIdx.x;
    const int lane = tid & 31;
    const int warp = tid >> 5;   // 8 warps; warp handles 8 local points

    // Load Wk, Wv into shared (vectorized); visibility covered by first loop sync
    {
        float4* d4 = (float4*)sW;
        const float4* k4 = (const float4*)Wk;
        const float4* v4 = (const float4*)Wv;
        for (int i = tid; i < 4096; i += 256) {
            d4[i] = k4[i];
            d4[4096 + i] = v4[i];
        }
    }
    const float4 g4  = ((const float4*)gamma)[lane];
    const float4 be4 = ((const float4*)beta)[lane];

    // Outer-product entry assignment: 4096 entries / 256 threads = 16 (4d x 4e)
    const int hh = tid >> 6;              // head 0..3
    const int idx = tid & 63;
    const int d0 = (idx >> 3) << 2;       // 0,4,...,28
    const int e0 = (idx & 7) << 2;        // 0,4,...,28

    unsigned long long acc[4][2];
#pragma unroll
    for (int i = 0; i < 4; i++) { acc[i][0] = 0ull; acc[i][1] = 0ull; }

    // Prologue: async-stage first chunk's X
    {
        const float* src = X + (size_t)blockIdx.x * 8192;
#pragma unroll
        for (int i = 0; i < 8; i++)
            cp16(sX + (tid + i * 256) * 4, src + (tid + i * 256) * 4);
        cp_commit();
    }

    int cur_b = -1;

    for (int chunk = blockIdx.x; chunk < NCHUNK1; chunk += NPART) {
        const int b = chunk >> 10;
        if (b != cur_b) {
            if (cur_b >= 0) {
                float* dst = g_part + ((size_t)cur_b * NPART + blockIdx.x) * 4096
                           + hh * 1024 + d0 * 32 + e0;
#pragma unroll
                for (int i = 0; i < 4; i++) {
                    float2 lo = unpk(acc[i][0]);
                    float2 hi = unpk(acc[i][1]);
                    *(float4*)(dst + i * 32) = make_float4(lo.x, lo.y, hi.x, hi.y);
                    acc[i][0] = 0ull; acc[i][1] = 0ull;
                }
            }
            cur_b = b;
        }

        cp_wait_all();
        __syncthreads();   // X ready; previous chunk's phase-3 sLN reads done

        // ---- Phase 1: matvec k = X@Wk, v = X@Wv (f32x2, 8 pts/warp, 4 ch/lane)
        unsigned long long ka[8][2], va[8][2];
#pragma unroll
        for (int p = 0; p < 8; p++) {
            ka[p][0] = ka[p][1] = 0ull;
            va[p][0] = va[p][1] = 0ull;
        }
        const float* wk = sW + 4 * lane;
        const float* wv = sW + 16384 + 4 * lane;
        const float* xb = sX + (warp << 3) * 128;
#pragma unroll 2
        for (int c = 0; c < 128; c += 2) {
            const ulonglong2 wk0 = *(const ulonglong2*)(wk + c * 128);
            const ulonglong2 wk1 = *(const ulonglong2*)(wk + c * 128 + 128);
            const ulonglong2 wv0 = *(const ulonglong2*)(wv + c * 128);
            const ulonglong2 wv1 = *(const ulonglong2*)(wv + c * 128 + 128);
            float2 xr[8];
#pragma unroll
            for (int p = 0; p < 8; p++)
                xr[p] = *(const float2*)(xb + p * 128 + c);
#pragma unroll
            for (int p = 0; p < 8; p++) {
                unsigned long long x0 = dup2(xr[p].x);
                unsigned long long x1 = dup2(xr[p].y);
                ka[p][0] = fma2(wk0.x, x0, ka[p][0]);
                ka[p][1] = fma2(wk0.y, x0, ka[p][1]);
                va[p][0] = fma2(wv0.x, x0, va[p][0]);
                va[p][1] = fma2(wv0.y, x0, va[p][1]);
                ka[p][0] = fma2(wk1.x, x1, ka[p][0]);
                ka[p][1] = fma2(wk1.y, x1, ka[p][1]);
                va[p][0] = fma2(wv1.x, x1, va[p][0]);
                va[p][1] = fma2(wv1.y, x1, va[p][1]);
            }
        }
        __syncthreads();   // all sX reads done -> safe to prefetch next chunk

        // ---- Prefetch next chunk's X (overlaps LN + outer product) ----
        {
            const int nxt = chunk + NPART;
            if (nxt < NCHUNK1) {
                const float* src = X + (size_t)nxt * 8192;
#pragma unroll
                for (int i = 0; i < 8; i++)
                    cp16(sX + (tid + i * 256) * 4, src + (tid + i * 256) * 4);
                cp_commit();
            }
        }

        // ---- Phase 2: LayerNorm over 128 channels, store kn/vn to sLN ----
#pragma unroll
        for (int p = 0; p < 8; p++) {
            float2 a0 = unpk(ka[p][0]), a1 = unpk(ka[p][1]);
            float2 b0 = unpk(va[p][0]), b1 = unpk(va[p][1]);
            float sk = a0.x + a0.y + a1.x + a1.y;
            float qk = a0.x * a0.x + a0.y * a0.y + a1.x * a1.x + a1.y * a1.y;
            float sv = b0.x + b0.y + b1.x + b1.y;
            float qv = b0.x * b0.x + b0.y * b0.y + b1.x * b1.x + b1.y * b1.y;
#pragma unroll
            for (int off = 16; off; off >>= 1) {
                sk += __shfl_xor_sync(0xffffffffu, sk, off);
                qk += __shfl_xor_sync(0xffffffffu, qk, off);
                sv += __shfl_xor_sync(0xffffffffu, sv, off);
                qv += __shfl_xor_sync(0xffffffffu, qv, off);
            }
            const float muk = sk * (1.f / 128.f);
            const float rk  = rsqrtf(qk * (1.f / 128.f) - muk * muk + 1e-5f);
            const float muv = sv * (1.f / 128.f);
            const float rv  = rsqrtf(qv * (1.f / 128.f) - muv * muv + 1e-5f);
            float* row = sLN + (((warp << 3) + p) << 8) + 4 * lane;  // [pt][256]
            *(float4*)row = make_float4((a0.x - muk) * rk * g4.x + be4.x,
                                        (a0.y - muk) * rk * g4.y + be4.y,
                                        (a1.x - muk) * rk * g4.z + be4.z,
                                        (a1.y - muk) * rk * g4.w + be4.w);
            *(float4*)(row + 128) = make_float4((b0.x - muv) * rv * g4.x + be4.x,
                                                (b0.y - muv) * rv * g4.y + be4.y,
                                                (b1.x - muv) * rv * g4.z + be4.z,
                                                (b1.y - muv) * rv * g4.w + be4.w);
        }
        __syncthreads();

        // ---- Phase 3: accumulate kv[h][d][e] += kn[h*32+d] * vn[h*32+e] ----
        const float* kb = sLN + hh * 32 + d0;
        const float* vb = sLN + 128 + hh * 32 + e0;
#pragma unroll 8
        for (int p = 0; p < 64; p++) {
            float4 kk = *(const float4*)(kb + p * 256);
            ulonglong2 vv = *(const ulonglong2*)(vb + p * 256);
            unsigned long long k0 = dup2(kk.x), k1 = dup2(kk.y);
            unsigned long long k2 = dup2(kk.z), k3 = dup2(kk.w);
            acc[0][0] = fma2(vv.x, k0, acc[0][0]); acc[0][1] = fma2(vv.y, k0, acc[0][1]);
            acc[1][0] = fma2(vv.x, k1, acc[1][0]); acc[1][1] = fma2(vv.y, k1, acc[1][1]);
            acc[2][0] = fma2(vv.x, k2, acc[2][0]); acc[2][1] = fma2(vv.y, k2, acc[2][1]);
            acc[3][0] = fma2(vv.x, k3, acc[3][0]); acc[3][1] = fma2(vv.y, k3, acc[3][1]);
        }
    }

    // final flush
    if (cur_b >= 0) {
        float* dst = g_part + ((size_t)cur_b * NPART + blockIdx.x) * 4096
                   + hh * 1024 + d0 * 32 + e0;
#pragma unroll
        for (int i = 0; i < 4; i++) {
            float2 lo = unpk(acc[i][0]);
            float2 hi = unpk(acc[i][1]);
            *(float4*)(dst + i * 32) = make_float4(lo.x, lo.y, hi.x, hi.y);
        }
    }
}

// ============================================================================
// Kernel 2a: reduce 148 per-CTA partials -> g_kv.  grid 64 x 256
// ============================================================================
__global__ void k2a_reduce()
{
    const int gid = blockIdx.x * 256 + threadIdx.x;   // [b][entry]
    const int b = gid >> 12;
    const int e = gid & 4095;
    const float* src = g_part + (size_t)b * NPART * 4096 + e;
    float s = 0.f;
#pragma unroll 4
    for (int j = 0; j < NPART; j++) s += src[(size_t)j * 4096];
    g_kv[gid] = s;
}

// ============================================================================
// Kernel 2b: Wq_eff[b][c'][e*4+h] = (1/N) * sum_d Wq[c'][h*32+d] * kv[b][h][d][e]
// ============================================================================
__global__ void k2b_fold(const float* __restrict__ Wq)
{
    const int gid = blockIdx.x * 256 + threadIdx.x;   // 0..65535
    const int b  = gid >> 14;
    const int r  = gid & 16383;
    const int cp = r >> 7;
    const int co = r & 127;
    const int e  = co >> 2;
    const int h  = co & 3;
    const float* wq = Wq + cp * 128 + h * 32;
    const float* kv = g_kv + b * 4096 + h * 1024 + e;
    float s = 0.f;
#pragma unroll
    for (int d = 0; d < 32; d++) s += wq[d] * kv[d * 32];
    g_wqeff[b * 16384 + cp * 128 + co] = s * (1.f / 65536.f);
}

// ============================================================================
// Kernel 3: out[p][:] = X[p][:] @ Wq_eff[b]
// 256 threads, 148 CTAs, 16 points/warp (chunk = 128 points), double-buffered
// cp.async X staging.  smem: sW 16384 + sX0 16384 + sX1 16384 = 192 KB
// ============================================================================
__global__ void __launch_bounds__(256, 1)
k3_out(const float* __restrict__ X, float* __restrict__ out)
{
    extern __shared__ float sm[];
    float* sW = sm;                       // 16384 floats
    float* sXb[2] = { sm + 16384, sm + 32768 };  // 16384 floats each (128 pts x 128)

    const int tid  = threadIdx.x;
    const int lane = tid & 31;
    const int warp = tid >> 5;

    // Prologue: prefetch first chunk
    {
        const float* src = X + (size_t)blockIdx.x * 16384;
        float* dst = sXb[0];
#pragma unroll
        for (int i = 0; i < 16; i++)
            cp16(dst + (tid + i * 256) * 4, src + (tid + i * 256) * 4);
        cp_commit();
    }

    int cur_b = -1;
    int it = 0;
    for (int chunk = blockIdx.x; chunk < NCHUNK3; chunk += NPART, it++) {
        const int cur = it & 1;
        const int b = chunk >> 9;

        cp_wait_all();
        __syncthreads();   // current X ready; all threads past previous compute

        // Prefetch next chunk into the other buffer (its readers are done)
        {
            const int nxt = chunk + NPART;
            if (nxt < NCHUNK3) {
                const float* src = X + (size_t)nxt * 16384;
                float* dst = sXb[cur ^ 1];
#pragma unroll
                for (int i = 0; i < 16; i++)
                    cp16(dst + (tid + i * 256) * 4, src + (tid + i * 256) * 4);
                cp_commit();
            }
        }

        if (b != cur_b) {
            float4* d4 = (float4*)sW;
            const float4* s4 = (const float4*)g_wqeff + b * 4096;
            for (int i = tid; i < 4096; i += 256) d4[i] = s4[i];
            cur_b = b;
            __syncthreads();
        }

        unsigned long long a[16][2];
#pragma unroll
        for (int p = 0; p < 16; p++) { a[p][0] = 0ull; a[p][1] = 0ull; }
        const float* w  = sW + 4 * lane;
        const float* xb = sXb[cur] + (warp << 4) * 128;
#pragma unroll 2
        for (int c = 0; c < 128; c += 2) {
            const ulonglong2 w0 = *(const ulonglong2*)(w + c * 128);
            const ulonglong2 w1 = *(const ulonglong2*)(w + c * 128 + 128);
            float2 xr[16];
#pragma unroll
            for (int p = 0; p < 16; p++)
                xr[p] = *(const float2*)(xb + p * 128 + c);
#pragma unroll
            for (int p = 0; p < 16; p++) {
                unsigned long long x0 = dup2(xr[p].x);
                unsigned long long x1 = dup2(xr[p].y);
                a[p][0] = fma2(w0.x, x0, a[p][0]);
                a[p][1] = fma2(w0.y, x0, a[p][1]);
                a[p][0] = fma2(w1.x, x1, a[p][0]);
                a[p][1] = fma2(w1.y, x1, a[p][1]);
            }
        }

        float4* o4 = (float4*)out + (size_t)chunk * 4096;
#pragma unroll
        for (int p = 0; p < 16; p++) {
            float2 lo = unpk(a[p][0]);
            float2 hi = unpk(a[p][1]);
            o4[((warp << 4) + p) * 32 + lane] = make_float4(lo.x, lo.y, hi.x, hi.y);
        }
    }
}

// ============================================================================
extern "C" void kernel_launch(void* const* d_in, const int* in_sizes, int n_in,
                              void* d_out, int out_size)
{
    (void)in_sizes; (void)n_in; (void)out_size;
    const float* X     = (const float*)d_in[0];
    const float* Wq    = (const float*)d_in[1];
    const float* Wk    = (const float*)d_in[2];
    const float* Wv    = (const float*)d_in[3];
    const float* gamma = (const float*)d_in[4];
    const float* beta  = (const float*)d_in[5];
    float* out = (float*)d_out;

    cudaFuncSetAttribute(k1_kv, cudaFuncAttributeMaxDynamicSharedMemorySize,
                         57344 * (int)sizeof(float));   // 224 KB
    cudaFuncSetAttribute(k3_out, cudaFuncAttributeMaxDynamicSharedMemorySize,
                         49152 * (int)sizeof(float));   // 192 KB

    k1_kv<<<NPART, 256, 57344 * sizeof(float)>>>(X, Wk, Wv, gamma, beta);
    k2a_reduce<<<64, 256>>>();
    k2b_fold<<<256, 256>>>(Wq);
    k3_out<<<NPART, 256, 49152 * sizeof(float)>>>(X, out);
}

// round 4
// speedup vs baseline: 1.3288x; 1.2362x over previous
#include <cuda_runtime.h>
#include <cuda_bf16.h>

// Problem constants
#define NPART    148     // persistent CTAs (one per SM)
#define NCHUNK1  4096    // K1: chunks of 64 points   (262144/64);  b = chunk>>10
#define NCHUNK3  2048    // K3: chunks of 128 points  (262144/128); b = chunk>>9

// Deterministic scratch (no cudaMalloc allowed)
__device__ float g_part[4 * NPART * 4096];   // per-CTA partial kv  [b][cta][h*1024+d*32+e]
__device__ float g_kv[4 * 4096];             // reduced kv          [b][h*1024+d*32+e]
__device__ float g_wqeff[4 * 16384];         // folded weights      [b][n*128 + c]  (n = e*4+h)

// ---- packed f32x2 helpers ----
__device__ __forceinline__ unsigned long long dup2(float x) {
    unsigned long long r;
    asm("mov.b64 %0, {%1, %1};" : "=l"(r) : "f"(x));
    return r;
}
__device__ __forceinline__ unsigned long long fma2(unsigned long long a,
                                                   unsigned long long b,
                                                   unsigned long long c) {
    unsigned long long d;
    asm("fma.rn.f32x2 %0, %1, %2, %3;" : "=l"(d) : "l"(a), "l"(b), "l"(c));
    return d;
}
__device__ __forceinline__ float2 unpk(unsigned long long a) {
    float2 f;
    asm("mov.b64 {%0, %1}, %2;" : "=f"(f.x), "=f"(f.y) : "l"(a));
    return f;
}

// ---- cp.async helpers ----
__device__ __forceinline__ void cp16(float* smem_dst, const float* gsrc) {
    unsigned s = (unsigned)__cvta_generic_to_shared(smem_dst);
    asm volatile("cp.async.cg.shared.global [%0], [%1], 16;" :: "r"(s), "l"(gsrc));
}
__device__ __forceinline__ void cp_commit() {
    asm volatile("cp.async.commit_group;");
}
__device__ __forceinline__ void cp_wait_all() {
    asm volatile("cp.async.wait_group 0;");
}

// ============================================================================
// Kernel 1 (unchanged this round): fused (X@Wk, X@Wv) -> LN -> kv partials
// ============================================================================
__global__ void __launch_bounds__(256, 1)
k1_kv(const float* __restrict__ X,
      const float* __restrict__ Wk, const float* __restrict__ Wv,
      const float* __restrict__ gamma, const float* __restrict__ beta)
{
    extern __shared__ float sm[];
    float* sW  = sm;            // 32768 floats
    float* sX  = sm + 32768;    // 8192 floats : 64 pts x 128
    float* sLN = sm + 40960;    // 16384 floats: kn/vn [64][256]

    const int tid  = threadIdx.x;
    const int lane = tid & 31;
    const int warp = tid >> 5;

    {
        float4* d4 = (float4*)sW;
        const float4* k4 = (const float4*)Wk;
        const float4* v4 = (const float4*)Wv;
        for (int i = tid; i < 4096; i += 256) {
            d4[i] = k4[i];
            d4[4096 + i] = v4[i];
        }
    }
    const float4 g4  = ((const float4*)gamma)[lane];
    const float4 be4 = ((const float4*)beta)[lane];

    const int hh = tid >> 6;
    const int idx = tid & 63;
    const int d0 = (idx >> 3) << 2;
    const int e0 = (idx & 7) << 2;

    unsigned long long acc[4][2];
#pragma unroll
    for (int i = 0; i < 4; i++) { acc[i][0] = 0ull; acc[i][1] = 0ull; }

    {
        const float* src = X + (size_t)blockIdx.x * 8192;
#pragma unroll
        for (int i = 0; i < 8; i++)
            cp16(sX + (tid + i * 256) * 4, src + (tid + i * 256) * 4);
        cp_commit();
    }

    int cur_b = -1;

    for (int chunk = blockIdx.x; chunk < NCHUNK1; chunk += NPART) {
        const int b = chunk >> 10;
        if (b != cur_b) {
            if (cur_b >= 0) {
                float* dst = g_part + ((size_t)cur_b * NPART + blockIdx.x) * 4096
                           + hh * 1024 + d0 * 32 + e0;
#pragma unroll
                for (int i = 0; i < 4; i++) {
                    float2 lo = unpk(acc[i][0]);
                    float2 hi = unpk(acc[i][1]);
                    *(float4*)(dst + i * 32) = make_float4(lo.x, lo.y, hi.x, hi.y);
                    acc[i][0] = 0ull; acc[i][1] = 0ull;
                }
            }
            cur_b = b;
        }

        cp_wait_all();
        __syncthreads();

        unsigned long long ka[8][2], va[8][2];
#pragma unroll
        for (int p = 0; p < 8; p++) {
            ka[p][0] = ka[p][1] = 0ull;
            va[p][0] = va[p][1] = 0ull;
        }
        const float* wk = sW + 4 * lane;
        const float* wv = sW + 16384 + 4 * lane;
        const float* xb = sX + (warp << 3) * 128;
#pragma unroll 2
        for (int c = 0; c < 128; c += 2) {
            const ulonglong2 wk0 = *(const ulonglong2*)(wk + c * 128);
            const ulonglong2 wk1 = *(const ulonglong2*)(wk + c * 128 + 128);
            const ulonglong2 wv0 = *(const ulonglong2*)(wv + c * 128);
            const ulonglong2 wv1 = *(const ulonglong2*)(wv + c * 128 + 128);
            float2 xr[8];
#pragma unroll
            for (int p = 0; p < 8; p++)
                xr[p] = *(const float2*)(xb + p * 128 + c);
#pragma unroll
            for (int p = 0; p < 8; p++) {
                unsigned long long x0 = dup2(xr[p].x);
                unsigned long long x1 = dup2(xr[p].y);
                ka[p][0] = fma2(wk0.x, x0, ka[p][0]);
                ka[p][1] = fma2(wk0.y, x0, ka[p][1]);
                va[p][0] = fma2(wv0.x, x0, va[p][0]);
                va[p][1] = fma2(wv0.y, x0, va[p][1]);
                ka[p][0] = fma2(wk1.x, x1, ka[p][0]);
                ka[p][1] = fma2(wk1.y, x1, ka[p][1]);
                va[p][0] = fma2(wv1.x, x1, va[p][0]);
                va[p][1] = fma2(wv1.y, x1, va[p][1]);
            }
        }
        __syncthreads();

        {
            const int nxt = chunk + NPART;
            if (nxt < NCHUNK1) {
                const float* src = X + (size_t)nxt * 8192;
#pragma unroll
                for (int i = 0; i < 8; i++)
                    cp16(sX + (tid + i * 256) * 4, src + (tid + i * 256) * 4);
                cp_commit();
            }
        }

#pragma unroll
        for (int p = 0; p < 8; p++) {
            float2 a0 = unpk(ka[p][0]), a1 = unpk(ka[p][1]);
            float2 b0 = unpk(va[p][0]), b1 = unpk(va[p][1]);
            float sk = a0.x + a0.y + a1.x + a1.y;
            float qk = a0.x * a0.x + a0.y * a0.y + a1.x * a1.x + a1.y * a1.y;
            float sv = b0.x + b0.y + b1.x + b1.y;
            float qv = b0.x * b0.x + b0.y * b0.y + b1.x * b1.x + b1.y * b1.y;
#pragma unroll
            for (int off = 16; off; off >>= 1) {
                sk += __shfl_xor_sync(0xffffffffu, sk, off);
                qk += __shfl_xor_sync(0xffffffffu, qk, off);
                sv += __shfl_xor_sync(0xffffffffu, sv, off);
                qv += __shfl_xor_sync(0xffffffffu, qv, off);
            }
            const float muk = sk * (1.f / 128.f);
            const float rk  = rsqrtf(qk * (1.f / 128.f) - muk * muk + 1e-5f);
            const float muv = sv * (1.f / 128.f);
            const float rv  = rsqrtf(qv * (1.f / 128.f) - muv * muv + 1e-5f);
            float* row = sLN + (((warp << 3) + p) << 8) + 4 * lane;
            *(float4*)row = make_float4((a0.x - muk) * rk * g4.x + be4.x,
                                        (a0.y - muk) * rk * g4.y + be4.y,
                                        (a1.x - muk) * rk * g4.z + be4.z,
                                        (a1.y - muk) * rk * g4.w + be4.w);
            *(float4*)(row + 128) = make_float4((b0.x - muv) * rv * g4.x + be4.x,
                                                (b0.y - muv) * rv * g4.y + be4.y,
                                                (b1.x - muv) * rv * g4.z + be4.z,
                                                (b1.y - muv) * rv * g4.w + be4.w);
        }
        __syncthreads();

        const float* kb = sLN + hh * 32 + d0;
        const float* vb = sLN + 128 + hh * 32 + e0;
#pragma unroll 8
        for (int p = 0; p < 64; p++) {
            float4 kk = *(const float4*)(kb + p * 256);
            ulonglong2 vv = *(const ulonglong2*)(vb + p * 256);
            unsigned long long k0 = dup2(kk.x), k1 = dup2(kk.y);
            unsigned long long k2 = dup2(kk.z), k3 = dup2(kk.w);
            acc[0][0] = fma2(vv.x, k0, acc[0][0]); acc[0][1] = fma2(vv.y, k0, acc[0][1]);
            acc[1][0] = fma2(vv.x, k1, acc[1][0]); acc[1][1] = fma2(vv.y, k1, acc[1][1]);
            acc[2][0] = fma2(vv.x, k2, acc[2][0]); acc[2][1] = fma2(vv.y, k2, acc[2][1]);
            acc[3][0] = fma2(vv.x, k3, acc[3][0]); acc[3][1] = fma2(vv.y, k3, acc[3][1]);
        }
    }

    if (cur_b >= 0) {
        float* dst = g_part + ((size_t)cur_b * NPART + blockIdx.x) * 4096
                   + hh * 1024 + d0 * 32 + e0;
#pragma unroll
        for (int i = 0; i < 4; i++) {
            float2 lo = unpk(acc[i][0]);
            float2 hi = unpk(acc[i][1]);
            *(float4*)(dst + i * 32) = make_float4(lo.x, lo.y, hi.x, hi.y);
        }
    }
}

// ============================================================================
// Kernel 2a: reduce 148 per-CTA partials -> g_kv.
// ============================================================================
__global__ void k2a_reduce()
{
    const int gid = blockIdx.x * 256 + threadIdx.x;
    const int b = gid >> 12;
    const int e = gid & 4095;
    const float* src = g_part + (size_t)b * NPART * 4096 + e;
    float s = 0.f;
#pragma unroll 4
    for (int j = 0; j < NPART; j++) s += src[(size_t)j * 4096];
    g_kv[gid] = s;
}

// ============================================================================
// Kernel 2b: Wq_eff[b][n][c] = (1/N) * sum_d Wq[c][h*32+d] * kv[b][h][d][e],
// n = e*4+h.  (Transposed layout = col-major B for K3's mma.sync.)
// ============================================================================
__global__ void k2b_fold(const float* __restrict__ Wq)
{
    const int gid = blockIdx.x * 256 + threadIdx.x;   // 0..65535
    const int b  = gid >> 14;
    const int r  = gid & 16383;
    const int cp = r >> 7;          // input channel c
    const int co = r & 127;         // output channel n = e*4+h
    const int e  = co >> 2;
    const int h  = co & 3;
    const float* wq = Wq + cp * 128 + h * 32;
    const float* kv = g_kv + b * 4096 + h * 1024 + e;
    float s = 0.f;
#pragma unroll
    for (int d = 0; d < 32; d++) s += wq[d] * kv[d * 32];
    g_wqeff[b * 16384 + co * 128 + cp] = s * (1.f / 65536.f);
}

// ============================================================================
// Kernel 3 (mma.sync, base sm_103 ISA): out = X @ Wq_eff[b]^T
//   bf16x3 error compensation: D = Xhi@Whi + Xhi@Wlo + Xlo@Whi (fp32 accum)
// 256 threads, 148 CTAs. Tiles in smem, swizzled for conflict-free LDS.
// smem: Whi 32K | Wlo 32K | Xhi 32K | Xlo 32K = 128 KB
// ============================================================================
#define K3S_W_HI 0
#define K3S_W_LO 32768
#define K3S_X_HI 65536
#define K3S_X_LO 98304
#define K3_SMEM  131072

// [128 rows][256 bytes] tile, XOR-swizzled at 16B granularity:
// bank(row, kb) = 4*(row&7) + (kb>>2)&3  -> all 32 banks distinct for
// fragment loads (8 consecutive rows x 4 lanes within 16B).
__device__ __forceinline__ unsigned sw_off(int row, int kbyte) {
    return (unsigned)((row << 8) + (kbyte ^ ((row & 7) << 4)));
}

__device__ __forceinline__ void mma_bf16(float* c,
                                         unsigned a0, unsigned a1, unsigned a2, unsigned a3,
                                         unsigned b0, unsigned b1) {
    asm volatile(
        "mma.sync.aligned.m16n8k16.row.col.f32.bf16.bf16.f32 "
        "{%0,%1,%2,%3}, {%4,%5,%6,%7}, {%8,%9}, {%0,%1,%2,%3};"
        : "+f"(c[0]), "+f"(c[1]), "+f"(c[2]), "+f"(c[3])
        : "r"(a0), "r"(a1), "r"(a2), "r"(a3), "r"(b0), "r"(b1));
}

// Convert a [128][128] fp32 row-major block into hi/lo bf16 swizzled tiles.
__device__ __forceinline__ void cvt_tile(const float* __restrict__ src,
                                         char* hi_base, char* lo_base, int tid) {
#pragma unroll
    for (int i = 0; i < 16; i++) {
        const int idx = tid + i * 256;
        const int row = idx >> 5;
        const int kb  = (idx & 31) << 3;       // byte offset of 4 bf16 cols
        const float4 x = *(const float4*)(src + idx * 4);
        __nv_bfloat162 h0 = __floats2bfloat162_rn(x.x, x.y);
        __nv_bfloat162 h1 = __floats2bfloat162_rn(x.z, x.w);
        float2 f0 = __bfloat1622float2(h0);
        float2 f1 = __bfloat1622float2(h1);
        __nv_bfloat162 l0 = __floats2bfloat162_rn(x.x - f0.x, x.y - f0.y);
        __nv_bfloat162 l1 = __floats2bfloat162_rn(x.z - f1.x, x.w - f1.y);
        const unsigned off = sw_off(row, kb);   // 8B chunk stays inside 16B block
        *(__nv_bfloat162*)(hi_base + off)     = h0;
        *(__nv_bfloat162*)(hi_base + off + 4) = h1;
        *(__nv_bfloat162*)(lo_base + off)     = l0;
        *(__nv_bfloat162*)(lo_base + off + 4) = l1;
    }
}

__global__ void __launch_bounds__(256, 1)
k3_out_mma(const float* __restrict__ X, float* __restrict__ out)
{
    extern __shared__ char smem[];
    const int tid  = threadIdx.x;
    const int lane = tid & 31;
    const int warp = tid >> 5;

    // warp tile: 64 rows x 32 cols (4 m-tiles of 16 x 4 n-tiles of 8)
    const int m0 = (warp & 1) * 64;
    const int n0 = (warp >> 1) * 32;
    const int qr = lane >> 2;   // group row 0..7
    const int qc = lane & 3;    // thread-in-group 0..3

    const char* xh = smem + K3S_X_HI;
    const char* xl = smem + K3S_X_LO;
    const char* wh = smem + K3S_W_HI;
    const char* wl = smem + K3S_W_LO;

    int cur_b = -1;
    for (int chunk = blockIdx.x; chunk < NCHUNK3; chunk += NPART) {
        const int b = chunk >> 9;
        __syncthreads();   // previous compute's LDS reads done before rewrite
        if (b != cur_b) {
            cvt_tile(g_wqeff + b * 16384, smem + K3S_W_HI, smem + K3S_W_LO, tid);
            cur_b = b;
        }
        cvt_tile(X + (size_t)chunk * 16384, smem + K3S_X_HI, smem + K3S_X_LO, tid);
        __syncthreads();

        float c[4][4][4];
#pragma unroll
        for (int mi = 0; mi < 4; mi++)
#pragma unroll
            for (int nj = 0; nj < 4; nj++)
#pragma unroll
                for (int z = 0; z < 4; z++) c[mi][nj][z] = 0.f;

#pragma unroll
        for (int ks = 0; ks < 8; ks++) {
            const int kb = ks * 32 + qc * 4;   // byte offset of this lane's k pair

            unsigned ah[4][4], al[4][4], bh[4][2], bl[4][2];
#pragma unroll
            for (int mi = 0; mi < 4; mi++) {
                const int r = m0 + mi * 16 + qr;
                const unsigned o0 = sw_off(r,     kb);
                const unsigned o1 = sw_off(r + 8, kb);
                const unsigned o2 = sw_off(r,     kb + 16);
                const unsigned o3 = sw_off(r + 8, kb + 16);
                ah[mi][0] = *(const unsigned*)(xh + o0);
                ah[mi][1] = *(const unsigned*)(xh + o1);
                ah[mi][2] = *(const unsigned*)(xh + o2);
                ah[mi][3] = *(const unsigned*)(xh + o3);
                al[mi][0] = *(const unsigned*)(xl + o0);
                al[mi][1] = *(const unsigned*)(xl + o1);
                al[mi][2] = *(const unsigned*)(xl + o2);
                al[mi][3] = *(const unsigned*)(xl + o3);
            }
#pragma unroll
            for (int nj = 0; nj < 4; nj++) {
                const int n = n0 + nj * 8 + qr;
                const unsigned o0 = sw_off(n, kb);
                const unsigned o1 = sw_off(n, kb + 16);
                bh[nj][0] = *(const unsigned*)(wh + o0);
                bh[nj][1] = *(const unsigned*)(wh + o1);
                bl[nj][0] = *(const unsigned*)(wl + o0);
                bl[nj][1] = *(const unsigned*)(wl + o1);
            }

#pragma unroll
            for (int mi = 0; mi < 4; mi++)
#pragma unroll
                for (int nj = 0; nj < 4; nj++)
                    mma_bf16(c[mi][nj], ah[mi][0], ah[mi][1], ah[mi][2], ah[mi][3],
                             bh[nj][0], bh[nj][1]);
#pragma unroll
            for (int mi = 0; mi < 4; mi++)
#pragma unroll
                for (int nj = 0; nj < 4; nj++)
                    mma_bf16(c[mi][nj], ah[mi][0], ah[mi][1], ah[mi][2], ah[mi][3],
                             bl[nj][0], bl[nj][1]);
#pragma unroll
            for (int mi = 0; mi < 4; mi++)
#pragma unroll
                for (int nj = 0; nj < 4; nj++)
                    mma_bf16(c[mi][nj], al[mi][0], al[mi][1], al[mi][2], al[mi][3],
                             bh[nj][0], bh[nj][1]);
        }

        // store accumulators
        float* obase = out + (size_t)chunk * 16384;
#pragma unroll
        for (int mi = 0; mi < 4; mi++) {
            const int r = m0 + mi * 16 + qr;
#pragma unroll
            for (int nj = 0; nj < 4; nj++) {
                const int col = n0 + nj * 8 + qc * 2;
                *(float2*)(obase + r * 128 + col) =
                    make_float2(c[mi][nj][0], c[mi][nj][1]);
                *(float2*)(obase + (r + 8) * 128 + col) =
                    make_float2(c[mi][nj][2], c[mi][nj][3]);
            }
        }
    }
}

// ============================================================================
extern "C" void kernel_launch(void* const* d_in, const int* in_sizes, int n_in,
                              void* d_out, int out_size)
{
    (void)in_sizes; (void)n_in; (void)out_size;
    const float* X     = (const float*)d_in[0];
    const float* Wq    = (const float*)d_in[1];
    const float* Wk    = (const float*)d_in[2];
    const float* Wv    = (const float*)d_in[3];
    const float* gamma = (const float*)d_in[4];
    const float* beta  = (const float*)d_in[5];
    float* out = (float*)d_out;

    cudaFuncSetAttribute(k1_kv, cudaFuncAttributeMaxDynamicSharedMemorySize,
                         57344 * (int)sizeof(float));   // 224 KB
    cudaFuncSetAttribute(k3_out_mma, cudaFuncAttributeMaxDynamicSharedMemorySize,
                         K3_SMEM);                      // 128 KB

    k1_kv<<<NPART, 256, 57344 * sizeof(float)>>>(X, Wk, Wv, gamma, beta);
    k2a_reduce<<<64, 256>>>();
    k2b_fold<<<256, 256>>>(Wq);
    k3_out_mma<<<NPART, 256, K3_SMEM>>>(X, out);
}

// round 5
// speedup vs baseline: 1.8108x; 1.3627x over previous
#include <cuda_runtime.h>
#include <cuda_bf16.h>

// Problem constants
#define NPART    148     // persistent CTAs (one per SM)
#define NCHUNK1  8192    // K1: chunks of 32 points  (262144/32);  b = chunk>>11
#define NCHUNK3  2048    // K3: chunks of 128 points (262144/128); b = chunk>>9

// Deterministic scratch (no cudaMalloc allowed)
__device__ float g_part[4 * NPART * 4096];   // per-CTA partial kv  [b][cta][h*1024+d*32+e]
__device__ float g_kv[4 * 4096];             // reduced kv          [b][h*1024+d*32+e]
__device__ float g_wqeff[4 * 16384];         // folded weights      [b][n*128 + c]  (n = e*4+h)

// ---- packed f32x2 helpers ----
__device__ __forceinline__ unsigned long long dup2(float x) {
    unsigned long long r;
    asm("mov.b64 %0, {%1, %1};" : "=l"(r) : "f"(x));
    return r;
}
__device__ __forceinline__ unsigned long long fma2(unsigned long long a,
                                                   unsigned long long b,
                                                   unsigned long long c) {
    unsigned long long d;
    asm("fma.rn.f32x2 %0, %1, %2, %3;" : "=l"(d) : "l"(a), "l"(b), "l"(c));
    return d;
}
__device__ __forceinline__ float2 unpk(unsigned long long a) {
    float2 f;
    asm("mov.b64 {%0, %1}, %2;" : "=f"(f.x), "=f"(f.y) : "l"(a));
    return f;
}

// ---- cp.async helpers ----
__device__ __forceinline__ void cp16(void* smem_dst, const float* gsrc) {
    unsigned s = (unsigned)__cvta_generic_to_shared(smem_dst);
    asm volatile("cp.async.cg.shared.global [%0], [%1], 16;" :: "r"(s), "l"(gsrc));
}
__device__ __forceinline__ void cp_commit() {
    asm volatile("cp.async.commit_group;");
}
__device__ __forceinline__ void cp_wait_all() {
    asm volatile("cp.async.wait_group 0;");
}

// ---- shared mma.sync infrastructure (validated in round 4's K3) ----
// bf16 tile [rows][256 bytes], XOR-swizzled at 16B granularity.
__device__ __forceinline__ unsigned sw_off(int row, int kbyte) {
    return (unsigned)((row << 8) + (kbyte ^ ((row & 7) << 4)));
}
// fp32 staging [rows][1024 bytes], XOR-swizzled at 16B granularity.
__device__ __forceinline__ unsigned skv_off(int row, int colb) {
    return (unsigned)((row << 10) + (colb ^ ((row & 7) << 4)));
}

__device__ __forceinline__ void mma_bf16(float* c,
                                         unsigned a0, unsigned a1, unsigned a2, unsigned a3,
                                         unsigned b0, unsigned b1) {
    asm volatile(
        "mma.sync.aligned.m16n8k16.row.col.f32.bf16.bf16.f32 "
        "{%0,%1,%2,%3}, {%4,%5,%6,%7}, {%8,%9}, {%0,%1,%2,%3};"
        : "+f"(c[0]), "+f"(c[1]), "+f"(c[2]), "+f"(c[3])
        : "r"(a0), "r"(a1), "r"(a2), "r"(a3), "r"(b0), "r"(b1));
}

// ============================================================================
// Kernel 1 (mma.sync): X@(Wk|Wv) via bf16x3 -> LN -> outer-product partials
// 256 threads, 148 CTAs.  smem layout (bytes):
//   WT_hi [256n][256B] 65536 | WT_lo 65536 | Xhi [32][256B] 8192 | Xlo 8192 |
//   sKV [32pt][256ch f32] 32768 | Xraw0 16384 | Xraw1 16384   = 212992 B
// ============================================================================
#define K1_WT_HI 0
#define K1_WT_LO 65536
#define K1_X_HI  131072
#define K1_X_LO  139264
#define K1_KV    147456
#define K1_XR0   180224
#define K1_XR1   196608
#define K1_SMEM  212992

__global__ void __launch_bounds__(256, 1)
k1_kv_mma(const float* __restrict__ X,
          const float* __restrict__ Wk, const float* __restrict__ Wv,
          const float* __restrict__ gamma, const float* __restrict__ beta)
{
    extern __shared__ char smem[];
    char* wth = smem + K1_WT_HI;
    char* wtl = smem + K1_WT_LO;
    char* xh  = smem + K1_X_HI;
    char* xl  = smem + K1_X_LO;
    char* skv = smem + K1_KV;
    float* xraw0 = (float*)(smem + K1_XR0);
    float* xraw1 = (float*)(smem + K1_XR1);

    const int tid  = threadIdx.x;
    const int lane = tid & 31;
    const int warp = tid >> 5;
    const int qr = lane >> 2;   // 0..7
    const int qc = lane & 3;    // 0..3

    // ---- One-time: transpose + bf16-split Wk|Wv into WT tiles (rows = out ch) ----
    for (int idx = tid; idx < 4096; idx += 256) {
        const int c  = idx >> 5;
        const int n4 = (idx & 31) << 2;
        const float4 wk = ((const float4*)Wk)[idx];
        const float4 wv = ((const float4*)Wv)[idx];
#pragma unroll
        for (int j = 0; j < 4; j++) {
            const float vk = (&wk.x)[j];
            const float vv = (&wv.x)[j];
            __nv_bfloat16 hk = __float2bfloat16(vk);
            __nv_bfloat16 hv = __float2bfloat16(vv);
            __nv_bfloat16 lk = __float2bfloat16(vk - __bfloat162float(hk));
            __nv_bfloat16 lv = __float2bfloat16(vv - __bfloat162float(hv));
            const unsigned ok = sw_off(n4 + j,       c * 2);
            const unsigned ov = sw_off(128 + n4 + j, c * 2);
            *(__nv_bfloat16*)(wth + ok) = hk;
            *(__nv_bfloat16*)(wtl + ok) = lk;
            *(__nv_bfloat16*)(wth + ov) = hv;
            *(__nv_bfloat16*)(wtl + ov) = lv;
        }
    }

    const float4 g4  = ((const float4*)gamma)[lane];
    const float4 be4 = ((const float4*)beta)[lane];

    // Outer-product entry assignment (16 entries per thread)
    const int hh = tid >> 6;
    const int idx2 = tid & 63;
    const int d0 = (idx2 >> 3) << 2;
    const int e0 = (idx2 & 7) << 2;
    const unsigned kcb = (unsigned)((hh * 32 + d0) * 4);         // k byte-col
    const unsigned vcb = (unsigned)(512 + (hh * 32 + e0) * 4);   // v byte-col

    unsigned long long acc[4][2];
#pragma unroll
    for (int i = 0; i < 4; i++) { acc[i][0] = 0ull; acc[i][1] = 0ull; }

    // MMA warp tile: 32 rows x 32 cols at n0
    const int n0 = warp * 32;

    // Prologue: prefetch first chunk's raw X (32 pts x 128 = 1024 float4)
    {
        const float* src = X + (size_t)blockIdx.x * 4096;
#pragma unroll
        for (int i = 0; i < 4; i++)
            cp16(xraw0 + (tid + i * 256) * 4, src + (tid + i * 256) * 4);
        cp_commit();
    }

    int cur_b = -1;
    int it = 0;
    for (int chunk = blockIdx.x; chunk < NCHUNK1; chunk += NPART, it++) {
        const int b = chunk >> 11;
        if (b != cur_b) {
            if (cur_b >= 0) {
                float* dst = g_part + ((size_t)cur_b * NPART + blockIdx.x) * 4096
                           + hh * 1024 + d0 * 32 + e0;
#pragma unroll
                for (int i = 0; i < 4; i++) {
                    float2 lo = unpk(acc[i][0]);
                    float2 hi = unpk(acc[i][1]);
                    *(float4*)(dst + i * 32) = make_float4(lo.x, lo.y, hi.x, hi.y);
                    acc[i][0] = 0ull; acc[i][1] = 0ull;
                }
            }
            cur_b = b;
        }

        cp_wait_all();   // this thread's raw X ready (same-thread produce/consume)
        const float* xr = (it & 1) ? xraw1 : xraw0;

        // ---- convert raw X -> Xhi/Xlo swizzled bf16 tiles ----
#pragma unroll
        for (int i = 0; i < 4; i++) {
            const int idx = tid + i * 256;
            const int row = idx >> 5;
            const int kb  = (idx & 31) << 3;
            const float4 x = ((const float4*)xr)[idx];
            __nv_bfloat162 h0 = __floats2bfloat162_rn(x.x, x.y);
            __nv_bfloat162 h1 = __floats2bfloat162_rn(x.z, x.w);
            float2 f0 = __bfloat1622float2(h0);
            float2 f1 = __bfloat1622float2(h1);
            __nv_bfloat162 l0 = __floats2bfloat162_rn(x.x - f0.x, x.y - f0.y);
            __nv_bfloat162 l1 = __floats2bfloat162_rn(x.z - f1.x, x.w - f1.y);
            const unsigned off = sw_off(row, kb);
            *(__nv_bfloat162*)(xh + off)     = h0;
            *(__nv_bfloat162*)(xh + off + 4) = h1;
            *(__nv_bfloat162*)(xl + off)     = l0;
            *(__nv_bfloat162*)(xl + off + 4) = l1;
        }

        // ---- prefetch next chunk's raw X into the other buffer ----
        {
            const int nxt = chunk + NPART;
            if (nxt < NCHUNK1) {
                const float* src = X + (size_t)nxt * 4096;
                float* dst = (it & 1) ? xraw0 : xraw1;
#pragma unroll
                for (int i = 0; i < 4; i++)
                    cp16(dst + (tid + i * 256) * 4, src + (tid + i * 256) * 4);
                cp_commit();
            }
        }
        __syncthreads();   // X tiles visible; prev iter's sKV readers done

        // ---- MMA: kv_raw[32pt][256ch] = X @ (Wk|Wv)  (bf16x3) ----
        float c[2][4][4];
#pragma unroll
        for (int mi = 0; mi < 2; mi++)
#pragma unroll
            for (int nj = 0; nj < 4; nj++)
#pragma unroll
                for (int z = 0; z < 4; z++) c[mi][nj][z] = 0.f;

#pragma unroll
        for (int ks = 0; ks < 8; ks++) {
            const int kb = ks * 32 + qc * 4;
            unsigned ah[2][4], al[2][4], bh[4][2], bl[4][2];
#pragma unroll
            for (int mi = 0; mi < 2; mi++) {
                const int r = mi * 16 + qr;
                const unsigned o0 = sw_off(r,     kb);
                const unsigned o1 = sw_off(r + 8, kb);
                const unsigned o2 = sw_off(r,     kb + 16);
                const unsigned o3 = sw_off(r + 8, kb + 16);
                ah[mi][0] = *(const unsigned*)(xh + o0);
                ah[mi][1] = *(const unsigned*)(xh + o1);
                ah[mi][2] = *(const unsigned*)(xh + o2);
                ah[mi][3] = *(const unsigned*)(xh + o3);
                al[mi][0] = *(const unsigned*)(xl + o0);
                al[mi][1] = *(const unsigned*)(xl + o1);
                al[mi][2] = *(const unsigned*)(xl + o2);
                al[mi][3] = *(const unsigned*)(xl + o3);
            }
#pragma unroll
            for (int nj = 0; nj < 4; nj++) {
                const int n = n0 + nj * 8 + qr;
                const unsigned o0 = sw_off(n, kb);
                const unsigned o1 = sw_off(n, kb + 16);
                bh[nj][0] = *(const unsigned*)(wth + o0);
                bh[nj][1] = *(const unsigned*)(wth + o1);
                bl[nj][0] = *(const unsigned*)(wtl + o0);
                bl[nj][1] = *(const unsigned*)(wtl + o1);
            }
#pragma unroll
            for (int mi = 0; mi < 2; mi++)
#pragma unroll
                for (int nj = 0; nj < 4; nj++) {
                    mma_bf16(c[mi][nj], ah[mi][0], ah[mi][1], ah[mi][2], ah[mi][3],
                             bh[nj][0], bh[nj][1]);
                    mma_bf16(c[mi][nj], ah[mi][0], ah[mi][1], ah[mi][2], ah[mi][3],
                             bl[nj][0], bl[nj][1]);
                    mma_bf16(c[mi][nj], al[mi][0], al[mi][1], al[mi][2], al[mi][3],
                             bh[nj][0], bh[nj][1]);
                }
        }

        // ---- store raw k|v to swizzled fp32 staging ----
#pragma unroll
        for (int mi = 0; mi < 2; mi++) {
            const int r = mi * 16 + qr;
#pragma unroll
            for (int nj = 0; nj < 4; nj++) {
                const int colb = (n0 + nj * 8 + qc * 2) * 4;
                *(float2*)(skv + skv_off(r,     colb)) = make_float2(c[mi][nj][0], c[mi][nj][1]);
                *(float2*)(skv + skv_off(r + 8, colb)) = make_float2(c[mi][nj][2], c[mi][nj][3]);
            }
        }
        __syncthreads();

        // ---- LayerNorm in place (8 warps x 4 points) ----
#pragma unroll
        for (int p = 0; p < 4; p++) {
            const int pt = (warp << 2) + p;
            float4* kp = (float4*)(skv + skv_off(pt, lane * 16));
            float4* vp = (float4*)(skv + skv_off(pt, 512 + lane * 16));
            const float4 kk = *kp;
            const float4 vv = *vp;
            float sk = kk.x + kk.y + kk.z + kk.w;
            float qk = kk.x * kk.x + kk.y * kk.y + kk.z * kk.z + kk.w * kk.w;
            float sv = vv.x + vv.y + vv.z + vv.w;
            float qv = vv.x * vv.x + vv.y * vv.y + vv.z * vv.z + vv.w * vv.w;
#pragma unroll
            for (int off = 16; off; off >>= 1) {
                sk += __shfl_xor_sync(0xffffffffu, sk, off);
                qk += __shfl_xor_sync(0xffffffffu, qk, off);
                sv += __shfl_xor_sync(0xffffffffu, sv, off);
                qv += __shfl_xor_sync(0xffffffffu, qv, off);
            }
            const float muk = sk * (1.f / 128.f);
            const float rk  = rsqrtf(qk * (1.f / 128.f) - muk * muk + 1e-5f);
            const float muv = sv * (1.f / 128.f);
            const float rv  = rsqrtf(qv * (1.f / 128.f) - muv * muv + 1e-5f);
            *kp = make_float4((kk.x - muk) * rk * g4.x + be4.x,
                              (kk.y - muk) * rk * g4.y + be4.y,
                              (kk.z - muk) * rk * g4.z + be4.z,
                              (kk.w - muk) * rk * g4.w + be4.w);
            *vp = make_float4((vv.x - muv) * rv * g4.x + be4.x,
                              (vv.y - muv) * rv * g4.y + be4.y,
                              (vv.z - muv) * rv * g4.z + be4.z,
                              (vv.w - muv) * rv * g4.w + be4.w);
        }
        __syncthreads();

        // ---- outer-product accumulate over 32 points ----
#pragma unroll 8
        for (int p = 0; p < 32; p++) {
            const float4 kk = *(const float4*)(skv + skv_off(p, kcb));
            const ulonglong2 vv = *(const ulonglong2*)(skv + skv_off(p, vcb));
            unsigned long long k0 = dup2(kk.x), k1 = dup2(kk.y);
            unsigned long long k2 = dup2(kk.z), k3 = dup2(kk.w);
            acc[0][0] = fma2(vv.x, k0, acc[0][0]); acc[0][1] = fma2(vv.y, k0, acc[0][1]);
            acc[1][0] = fma2(vv.x, k1, acc[1][0]); acc[1][1] = fma2(vv.y, k1, acc[1][1]);
            acc[2][0] = fma2(vv.x, k2, acc[2][0]); acc[2][1] = fma2(vv.y, k2, acc[2][1]);
            acc[3][0] = fma2(vv.x, k3, acc[3][0]); acc[3][1] = fma2(vv.y, k3, acc[3][1]);
        }
    }

    if (cur_b >= 0) {
        float* dst = g_part + ((size_t)cur_b * NPART + blockIdx.x) * 4096
                   + hh * 1024 + d0 * 32 + e0;
#pragma unroll
        for (int i = 0; i < 4; i++) {
            float2 lo = unpk(acc[i][0]);
            float2 hi = unpk(acc[i][1]);
            *(float4*)(dst + i * 32) = make_float4(lo.x, lo.y, hi.x, hi.y);
        }
    }
}

// ============================================================================
// Kernel 2a: reduce 148 per-CTA partials -> g_kv.
// ============================================================================
__global__ void k2a_reduce()
{
    const int gid = blockIdx.x * 256 + threadIdx.x;
    const int b = gid >> 12;
    const int e = gid & 4095;
    const float* src = g_part + (size_t)b * NPART * 4096 + e;
    float s = 0.f;
#pragma unroll 4
    for (int j = 0; j < NPART; j++) s += src[(size_t)j * 4096];
    g_kv[gid] = s;
}

// ============================================================================
// Kernel 2b: Wq_eff[b][n][c] = (1/N) * sum_d Wq[c][h*32+d] * kv[b][h][d][e]
// ============================================================================
__global__ void k2b_fold(const float* __restrict__ Wq)
{
    const int gid = blockIdx.x * 256 + threadIdx.x;   // 0..65535
    const int b  = gid >> 14;
    const int r  = gid & 16383;
    const int cp = r >> 7;
    const int co = r & 127;
    const int e  = co >> 2;
    const int h  = co & 3;
    const float* wq = Wq + cp * 128 + h * 32;
    const float* kv = g_kv + b * 4096 + h * 1024 + e;
    float s = 0.f;
#pragma unroll
    for (int d = 0; d < 32; d++) s += wq[d] * kv[d * 32];
    g_wqeff[b * 16384 + co * 128 + cp] = s * (1.f / 65536.f);
}

// ============================================================================
// Kernel 3 (unchanged from round 4): out = X @ Wq_eff[b]^T via mma.sync bf16x3
// ============================================================================
#define K3S_W_HI 0
#define K3S_W_LO 32768
#define K3S_X_HI 65536
#define K3S_X_LO 98304
#define K3_SMEM  131072

__device__ __forceinline__ void cvt_tile(const float* __restrict__ src,
                                         char* hi_base, char* lo_base, int tid) {
#pragma unroll
    for (int i = 0; i < 16; i++) {
        const int idx = tid + i * 256;
        const int row = idx >> 5;
        const int kb  = (idx & 31) << 3;
        const float4 x = *(const float4*)(src + idx * 4);
        __nv_bfloat162 h0 = __floats2bfloat162_rn(x.x, x.y);
        __nv_bfloat162 h1 = __floats2bfloat162_rn(x.z, x.w);
        float2 f0 = __bfloat1622float2(h0);
        float2 f1 = __bfloat1622float2(h1);
        __nv_bfloat162 l0 = __floats2bfloat162_rn(x.x - f0.x, x.y - f0.y);
        __nv_bfloat162 l1 = __floats2bfloat162_rn(x.z - f1.x, x.w - f1.y);
        const unsigned off = sw_off(row, kb);
        *(__nv_bfloat162*)(hi_base + off)     = h0;
        *(__nv_bfloat162*)(hi_base + off + 4) = h1;
        *(__nv_bfloat162*)(lo_base + off)     = l0;
        *(__nv_bfloat162*)(lo_base + off + 4) = l1;
    }
}

__global__ void __launch_bounds__(256, 1)
k3_out_mma(const float* __restrict__ X, float* __restrict__ out)
{
    extern __shared__ char smem[];
    const int tid  = threadIdx.x;
    const int lane = tid & 31;
    const int warp = tid >> 5;

    const int m0 = (warp & 1) * 64;
    const int n0 = (warp >> 1) * 32;
    const int qr = lane >> 2;
    const int qc = lane & 3;

    const char* xh = smem + K3S_X_HI;
    const char* xl = smem + K3S_X_LO;
    const char* wh = smem + K3S_W_HI;
    const char* wl = smem + K3S_W_LO;

    int cur_b = -1;
    for (int chunk = blockIdx.x; chunk < NCHUNK3; chunk += NPART) {
        const int b = chunk >> 9;
        __syncthreads();
        if (b != cur_b) {
            cvt_tile(g_wqeff + b * 16384, smem + K3S_W_HI, smem + K3S_W_LO, tid);
            cur_b = b;
        }
        cvt_tile(X + (size_t)chunk * 16384, smem + K3S_X_HI, smem + K3S_X_LO, tid);
        __syncthreads();

        float c[4][4][4];
#pragma unroll
        for (int mi = 0; mi < 4; mi++)
#pragma unroll
            for (int nj = 0; nj < 4; nj++)
#pragma unroll
                for (int z = 0; z < 4; z++) c[mi][nj][z] = 0.f;

#pragma unroll
        for (int ks = 0; ks < 8; ks++) {
            const int kb = ks * 32 + qc * 4;
            unsigned ah[4][4], al[4][4], bh[4][2], bl[4][2];
#pragma unroll
            for (int mi = 0; mi < 4; mi++) {
                const int r = m0 + mi * 16 + qr;
                const unsigned o0 = sw_off(r,     kb);
                const unsigned o1 = sw_off(r + 8, kb);
                const unsigned o2 = sw_off(r,     kb + 16);
                const unsigned o3 = sw_off(r + 8, kb + 16);
                ah[mi][0] = *(const unsigned*)(xh + o0);
                ah[mi][1] = *(const unsigned*)(xh + o1);
                ah[mi][2] = *(const unsigned*)(xh + o2);
                ah[mi][3] = *(const unsigned*)(xh + o3);
                al[mi][0] = *(const unsigned*)(xl + o0);
                al[mi][1] = *(const unsigned*)(xl + o1);
                al[mi][2] = *(const unsigned*)(xl + o2);
                al[mi][3] = *(const unsigned*)(xl + o3);
            }
#pragma unroll
            for (int nj = 0; nj < 4; nj++) {
                const int n = n0 + nj * 8 + qr;
                const unsigned o0 = sw_off(n, kb);
                const unsigned o1 = sw_off(n, kb + 16);
                bh[nj][0] = *(const unsigned*)(wh + o0);
                bh[nj][1] = *(const unsigned*)(wh + o1);
                bl[nj][0] = *(const unsigned*)(wl + o0);
                bl[nj][1] = *(const unsigned*)(wl + o1);
            }

#pragma unroll
            for (int mi = 0; mi < 4; mi++)
#pragma unroll
                for (int nj = 0; nj < 4; nj++)
                    mma_bf16(c[mi][nj], ah[mi][0], ah[mi][1], ah[mi][2], ah[mi][3],
                             bh[nj][0], bh[nj][1]);
#pragma unroll
            for (int mi = 0; mi < 4; mi++)
#pragma unroll
                for (int nj = 0; nj < 4; nj++)
                    mma_bf16(c[mi][nj], ah[mi][0], ah[mi][1], ah[mi][2], ah[mi][3],
                             bl[nj][0], bl[nj][1]);
#pragma unroll
            for (int mi = 0; mi < 4; mi++)
#pragma unroll
                for (int nj = 0; nj < 4; nj++)
                    mma_bf16(c[mi][nj], al[mi][0], al[mi][1], al[mi][2], al[mi][3],
                             bh[nj][0], bh[nj][1]);
        }

        float* obase = out + (size_t)chunk * 16384;
#pragma unroll
        for (int mi = 0; mi < 4; mi++) {
            const int r = m0 + mi * 16 + qr;
#pragma unroll
            for (int nj = 0; nj < 4; nj++) {
                const int col = n0 + nj * 8 + qc * 2;
                *(float2*)(obase + r * 128 + col) =
                    make_float2(c[mi][nj][0], c[mi][nj][1]);
                *(float2*)(obase + (r + 8) * 128 + col) =
                    make_float2(c[mi][nj][2], c[mi][nj][3]);
            }
        }
    }
}

// ============================================================================
extern "C" void kernel_launch(void* const* d_in, const int* in_sizes, int n_in,
                              void* d_out, int out_size)
{
    (void)in_sizes; (void)n_in; (void)out_size;
    const float* X     = (const float*)d_in[0];
    const float* Wq    = (const float*)d_in[1];
    const float* Wk    = (const float*)d_in[2];
    const float* Wv    = (const float*)d_in[3];
    const float* gamma = (const float*)d_in[4];
    const float* beta  = (const float*)d_in[5];
    float* out = (float*)d_out;

    cudaFuncSetAttribute(k1_kv_mma, cudaFuncAttributeMaxDynamicSharedMemorySize,
                         K1_SMEM);    // 208 KB
    cudaFuncSetAttribute(k3_out_mma, cudaFuncAttributeMaxDynamicSharedMemorySize,
                         K3_SMEM);    // 128 KB

    k1_kv_mma<<<NPART, 256, K1_SMEM>>>(X, Wk, Wv, gamma, beta);
    k2a_reduce<<<64, 256>>>();
    k2b_fold<<<256, 256>>>(Wq);
    k3_out_mma<<<NPART, 256, K3_SMEM>>>(X, out);
}

// round 6
// speedup vs baseline: 1.8732x; 1.0345x over previous
#include <cuda_runtime.h>
#include <cuda_bf16.h>

// Problem constants
#define NPART    148     // persistent CTAs (one per SM)
#define NCHUNK1  4096    // K1: chunks of 64 points  (262144/64);  b = chunk>>10
#define NCHUNK3  2048    // K3: chunks of 128 points (262144/128); b = chunk>>9

// Deterministic scratch (no cudaMalloc allowed)
__device__ float g_part[4 * NPART * 4096];   // per-CTA partial kv  [b][cta][h*1024+d*32+e]
__device__ float g_kv[4 * 4096];             // reduced kv          [b][h*1024+d*32+e]
__device__ float g_wqeff[4 * 16384];         // folded weights      [b][n*128 + c]  (n = e*4+h)

// ---- packed f32x2 helpers ----
__device__ __forceinline__ unsigned long long dup2(float x) {
    unsigned long long r;
    asm("mov.b64 %0, {%1, %1};" : "=l"(r) : "f"(x));
    return r;
}
__device__ __forceinline__ unsigned long long fma2(unsigned long long a,
                                                   unsigned long long b,
                                                   unsigned long long c) {
    unsigned long long d;
    asm("fma.rn.f32x2 %0, %1, %2, %3;" : "=l"(d) : "l"(a), "l"(b), "l"(c));
    return d;
}
__device__ __forceinline__ float2 unpk(unsigned long long a) {
    float2 f;
    asm("mov.b64 {%0, %1}, %2;" : "=f"(f.x), "=f"(f.y) : "l"(a));
    return f;
}

// ---- cp.async helpers ----
__device__ __forceinline__ void cp16(void* smem_dst, const float* gsrc) {
    unsigned s = (unsigned)__cvta_generic_to_shared(smem_dst);
    asm volatile("cp.async.cg.shared.global [%0], [%1], 16;" :: "r"(s), "l"(gsrc));
}
__device__ __forceinline__ void cp_commit() {
    asm volatile("cp.async.commit_group;");
}
__device__ __forceinline__ void cp_wait_all() {
    asm volatile("cp.async.wait_group 0;");
}

// ---- shared mma.sync infrastructure ----
// bf16 tile [rows][256 bytes], XOR-swizzled at 16B granularity.
__device__ __forceinline__ unsigned sw_off(int row, int kbyte) {
    return (unsigned)((row << 8) + (kbyte ^ ((row & 7) << 4)));
}
// fp32 staging [rows][1024 bytes], XOR-swizzled at 16B granularity.
__device__ __forceinline__ unsigned skv_off(int row, int colb) {
    return (unsigned)((row << 10) + (colb ^ ((row & 7) << 4)));
}

__device__ __forceinline__ void mma_bf16(float* c,
                                         unsigned a0, unsigned a1, unsigned a2, unsigned a3,
                                         unsigned b0, unsigned b1) {
    asm volatile(
        "mma.sync.aligned.m16n8k16.row.col.f32.bf16.bf16.f32 "
        "{%0,%1,%2,%3}, {%4,%5,%6,%7}, {%8,%9}, {%0,%1,%2,%3};"
        : "+f"(c[0]), "+f"(c[1]), "+f"(c[2]), "+f"(c[3])
        : "r"(a0), "r"(a1), "r"(a2), "r"(a3), "r"(b0), "r"(b1));
}

// ============================================================================
// Kernel 1 (mma.sync): X@(Wk|Wv) bf16x3 -> LN -> outer-product partials
// 64-point chunks, register-resident X prefetch (no raw smem staging).
// smem: WT_hi 64K | WT_lo 64K | Xhi 16K | Xlo 16K | sKV 64K = 224 KB
// ============================================================================
#define K1_WT_HI 0
#define K1_WT_LO 65536
#define K1_X_HI  131072
#define K1_X_LO  147456
#define K1_KV    163840
#define K1_SMEM  229376

__global__ void __launch_bounds__(256, 1)
k1_kv_mma(const float* __restrict__ X,
          const float* __restrict__ Wk, const float* __restrict__ Wv,
          const float* __restrict__ gamma, const float* __restrict__ beta)
{
    extern __shared__ char smem[];
    char* wth = smem + K1_WT_HI;
    char* wtl = smem + K1_WT_LO;
    char* xh  = smem + K1_X_HI;
    char* xl  = smem + K1_X_LO;
    char* skv = smem + K1_KV;

    const int tid  = threadIdx.x;
    const int lane = tid & 31;
    const int warp = tid >> 5;
    const int qr = lane >> 2;   // 0..7
    const int qc = lane & 3;    // 0..3

    // ---- One-time: transpose + bf16-split Wk|Wv into WT tiles (rows = out ch) ----
    for (int idx = tid; idx < 4096; idx += 256) {
        const int c  = idx >> 5;
        const int n4 = (idx & 31) << 2;
        const float4 wk = ((const float4*)Wk)[idx];
        const float4 wv = ((const float4*)Wv)[idx];
#pragma unroll
        for (int j = 0; j < 4; j++) {
            const float vk = (&wk.x)[j];
            const float vv = (&wv.x)[j];
            __nv_bfloat16 hk = __float2bfloat16(vk);
            __nv_bfloat16 hv = __float2bfloat16(vv);
            __nv_bfloat16 lk = __float2bfloat16(vk - __bfloat162float(hk));
            __nv_bfloat16 lv = __float2bfloat16(vv - __bfloat162float(hv));
            const unsigned ok = sw_off(n4 + j,       c * 2);
            const unsigned ov = sw_off(128 + n4 + j, c * 2);
            *(__nv_bfloat16*)(wth + ok) = hk;
            *(__nv_bfloat16*)(wtl + ok) = lk;
            *(__nv_bfloat16*)(wth + ov) = hv;
            *(__nv_bfloat16*)(wtl + ov) = lv;
        }
    }

    const float4 g4  = ((const float4*)gamma)[lane];
    const float4 be4 = ((const float4*)beta)[lane];

    // Outer-product entry assignment (16 entries per thread)
    const int hh = tid >> 6;
    const int idx2 = tid & 63;
    const int d0 = (idx2 >> 3) << 2;
    const int e0 = (idx2 & 7) << 2;
    const unsigned kcb = (unsigned)((hh * 32 + d0) * 4);         // k byte-col
    const unsigned vcb = (unsigned)(512 + (hh * 32 + e0) * 4);   // v byte-col

    unsigned long long acc[4][2];
#pragma unroll
    for (int i = 0; i < 4; i++) { acc[i][0] = 0ull; acc[i][1] = 0ull; }

    // MMA warp tile: 64 rows x 32 cols at n0
    const int n0 = warp * 32;

    // Prologue: LDG first chunk's raw X into registers (64 pts x 128 = 2048 f4)
    float4 xr[8];
    {
        const float4* src = (const float4*)X + (size_t)blockIdx.x * 2048;
#pragma unroll
        for (int i = 0; i < 8; i++) xr[i] = src[tid + i * 256];
    }

    int cur_b = -1;
    for (int chunk = blockIdx.x; chunk < NCHUNK1; chunk += NPART) {
        const int b = chunk >> 10;
        if (b != cur_b) {
            if (cur_b >= 0) {
                float* dst = g_part + ((size_t)cur_b * NPART + blockIdx.x) * 4096
                           + hh * 1024 + d0 * 32 + e0;
#pragma unroll
                for (int i = 0; i < 4; i++) {
                    float2 lo = unpk(acc[i][0]);
                    float2 hi = unpk(acc[i][1]);
                    *(float4*)(dst + i * 32) = make_float4(lo.x, lo.y, hi.x, hi.y);
                    acc[i][0] = 0ull; acc[i][1] = 0ull;
                }
            }
            cur_b = b;
        }

        // ---- convert register-resident raw X -> Xhi/Xlo swizzled bf16 tiles ----
#pragma unroll
        for (int i = 0; i < 8; i++) {
            const int idx = tid + i * 256;
            const int row = idx >> 5;          // 0..63
            const int kb  = (idx & 31) << 3;
            const float4 x = xr[i];
            __nv_bfloat162 h0 = __floats2bfloat162_rn(x.x, x.y);
            __nv_bfloat162 h1 = __floats2bfloat162_rn(x.z, x.w);
            float2 f0 = __bfloat1622float2(h0);
            float2 f1 = __bfloat1622float2(h1);
            __nv_bfloat162 l0 = __floats2bfloat162_rn(x.x - f0.x, x.y - f0.y);
            __nv_bfloat162 l1 = __floats2bfloat162_rn(x.z - f1.x, x.w - f1.y);
            const unsigned off = sw_off(row, kb);
            *(__nv_bfloat162*)(xh + off)     = h0;
            *(__nv_bfloat162*)(xh + off + 4) = h1;
            *(__nv_bfloat162*)(xl + off)     = l0;
            *(__nv_bfloat162*)(xl + off + 4) = l1;
        }

        // ---- prefetch next chunk's raw X into registers (hides under MMA/LN) ----
        {
            const int nxt = chunk + NPART;
            if (nxt < NCHUNK1) {
                const float4* src = (const float4*)X + (size_t)nxt * 2048;
#pragma unroll
                for (int i = 0; i < 8; i++) xr[i] = src[tid + i * 256];
            }
        }
        __syncthreads();   // tiles visible; also orders prev outer before sKV store

        // ---- MMA: kv_raw[64pt][256ch] = X @ (Wk|Wv)  (bf16x3) ----
        float c[4][4][4];
#pragma unroll
        for (int mi = 0; mi < 4; mi++)
#pragma unroll
            for (int nj = 0; nj < 4; nj++)
#pragma unroll
                for (int z = 0; z < 4; z++) c[mi][nj][z] = 0.f;

#pragma unroll
        for (int ks = 0; ks < 8; ks++) {
            const int kb = ks * 32 + qc * 4;
            unsigned ah[4][4], al[4][4], bh[4][2], bl[4][2];
#pragma unroll
            for (int mi = 0; mi < 4; mi++) {
                const int r = mi * 16 + qr;
                const unsigned o0 = sw_off(r,     kb);
                const unsigned o1 = sw_off(r + 8, kb);
                const unsigned o2 = sw_off(r,     kb + 16);
                const unsigned o3 = sw_off(r + 8, kb + 16);
                ah[mi][0] = *(const unsigned*)(xh + o0);
                ah[mi][1] = *(const unsigned*)(xh + o1);
                ah[mi][2] = *(const unsigned*)(xh + o2);
                ah[mi][3] = *(const unsigned*)(xh + o3);
                al[mi][0] = *(const unsigned*)(xl + o0);
                al[mi][1] = *(const unsigned*)(xl + o1);
                al[mi][2] = *(const unsigned*)(xl + o2);
                al[mi][3] = *(const unsigned*)(xl + o3);
            }
#pragma unroll
            for (int nj = 0; nj < 4; nj++) {
                const int n = n0 + nj * 8 + qr;
                const unsigned o0 = sw_off(n, kb);
                const unsigned o1 = sw_off(n, kb + 16);
                bh[nj][0] = *(const unsigned*)(wth + o0);
                bh[nj][1] = *(const unsigned*)(wth + o1);
                bl[nj][0] = *(const unsigned*)(wtl + o0);
                bl[nj][1] = *(const unsigned*)(wtl + o1);
            }
#pragma unroll
            for (int mi = 0; mi < 4; mi++)
#pragma unroll
                for (int nj = 0; nj < 4; nj++) {
                    mma_bf16(c[mi][nj], ah[mi][0], ah[mi][1], ah[mi][2], ah[mi][3],
                             bh[nj][0], bh[nj][1]);
                    mma_bf16(c[mi][nj], ah[mi][0], ah[mi][1], ah[mi][2], ah[mi][3],
                             bl[nj][0], bl[nj][1]);
                    mma_bf16(c[mi][nj], al[mi][0], al[mi][1], al[mi][2], al[mi][3],
                             bh[nj][0], bh[nj][1]);
                }
        }

        // ---- store raw k|v to swizzled fp32 staging ----
#pragma unroll
        for (int mi = 0; mi < 4; mi++) {
            const int r = mi * 16 + qr;
#pragma unroll
            for (int nj = 0; nj < 4; nj++) {
                const int colb = (n0 + nj * 8 + qc * 2) * 4;
                *(float2*)(skv + skv_off(r,     colb)) = make_float2(c[mi][nj][0], c[mi][nj][1]);
                *(float2*)(skv + skv_off(r + 8, colb)) = make_float2(c[mi][nj][2], c[mi][nj][3]);
            }
        }
        __syncthreads();

        // ---- LayerNorm in place (8 warps x 8 points) ----
#pragma unroll
        for (int p = 0; p < 8; p++) {
            const int pt = (warp << 3) + p;
            float4* kp = (float4*)(skv + skv_off(pt, lane * 16));
            float4* vp = (float4*)(skv + skv_off(pt, 512 + lane * 16));
            const float4 kk = *kp;
            const float4 vv = *vp;
            float sk = kk.x + kk.y + kk.z + kk.w;
            float qk = kk.x * kk.x + kk.y * kk.y + kk.z * kk.z + kk.w * kk.w;
            float sv = vv.x + vv.y + vv.z + vv.w;
            float qv = vv.x * vv.x + vv.y * vv.y + vv.z * vv.z + vv.w * vv.w;
#pragma unroll
            for (int off = 16; off; off >>= 1) {
                sk += __shfl_xor_sync(0xffffffffu, sk, off);
                qk += __shfl_xor_sync(0xffffffffu, qk, off);
                sv += __shfl_xor_sync(0xffffffffu, sv, off);
                qv += __shfl_xor_sync(0xffffffffu, qv, off);
            }
            const float muk = sk * (1.f / 128.f);
            const float rk  = rsqrtf(qk * (1.f / 128.f) - muk * muk + 1e-5f);
            const float muv = sv * (1.f / 128.f);
            const float rv  = rsqrtf(qv * (1.f / 128.f) - muv * muv + 1e-5f);
            *kp = make_float4((kk.x - muk) * rk * g4.x + be4.x,
                              (kk.y - muk) * rk * g4.y + be4.y,
                              (kk.z - muk) * rk * g4.z + be4.z,
                              (kk.w - muk) * rk * g4.w + be4.w);
            *vp = make_float4((vv.x - muv) * rv * g4.x + be4.x,
                              (vv.y - muv) * rv * g4.y + be4.y,
                              (vv.z - muv) * rv * g4.z + be4.z,
                              (vv.w - muv) * rv * g4.w + be4.w);
        }
        __syncthreads();

        // ---- outer-product accumulate over 64 points ----
#pragma unroll 8
        for (int p = 0; p < 64; p++) {
            const float4 kk = *(const float4*)(skv + skv_off(p, kcb));
            const ulonglong2 vv = *(const ulonglong2*)(skv + skv_off(p, vcb));
            unsigned long long k0 = dup2(kk.x), k1 = dup2(kk.y);
            unsigned long long k2 = dup2(kk.z), k3 = dup2(kk.w);
            acc[0][0] = fma2(vv.x, k0, acc[0][0]); acc[0][1] = fma2(vv.y, k0, acc[0][1]);
            acc[1][0] = fma2(vv.x, k1, acc[1][0]); acc[1][1] = fma2(vv.y, k1, acc[1][1]);
            acc[2][0] = fma2(vv.x, k2, acc[2][0]); acc[2][1] = fma2(vv.y, k2, acc[2][1]);
            acc[3][0] = fma2(vv.x, k3, acc[3][0]); acc[3][1] = fma2(vv.y, k3, acc[3][1]);
        }
    }

    if (cur_b >= 0) {
        float* dst = g_part + ((size_t)cur_b * NPART + blockIdx.x) * 4096
                   + hh * 1024 + d0 * 32 + e0;
#pragma unroll
        for (int i = 0; i < 4; i++) {
            float2 lo = unpk(acc[i][0]);
            float2 hi = unpk(acc[i][1]);
            *(float4*)(dst + i * 32) = make_float4(lo.x, lo.y, hi.x, hi.y);
        }
    }
}

// ============================================================================
// Kernel 2a: reduce 148 per-CTA partials -> g_kv.
// ============================================================================
__global__ void k2a_reduce()
{
    const int gid = blockIdx.x * 256 + threadIdx.x;
    const int b = gid >> 12;
    const int e = gid & 4095;
    const float* src = g_part + (size_t)b * NPART * 4096 + e;
    float s = 0.f;
#pragma unroll 4
    for (int j = 0; j < NPART; j++) s += src[(size_t)j * 4096];
    g_kv[gid] = s;
}

// ============================================================================
// Kernel 2b: Wq_eff[b][n][c] = (1/N) * sum_d Wq[c][h*32+d] * kv[b][h][d][e]
// ============================================================================
__global__ void k2b_fold(const float* __restrict__ Wq)
{
    const int gid = blockIdx.x * 256 + threadIdx.x;   // 0..65535
    const int b  = gid >> 14;
    const int r  = gid & 16383;
    const int cp = r >> 7;
    const int co = r & 127;
    const int e  = co >> 2;
    const int h  = co & 3;
    const float* wq = Wq + cp * 128 + h * 32;
    const float* kv = g_kv + b * 4096 + h * 1024 + e;
    float s = 0.f;
#pragma unroll
    for (int d = 0; d < 32; d++) s += wq[d] * kv[d * 32];
    g_wqeff[b * 16384 + co * 128 + cp] = s * (1.f / 65536.f);
}

// ============================================================================
// Kernel 3 (mma.sync + cp.async pipeline): out = X @ Wq_eff[b]^T  (bf16x3)
// smem: Whi 32K | Wlo 32K | Xhi 32K | Xlo 32K | raw 64K = 192 KB
// ============================================================================
#define K3S_W_HI 0
#define K3S_W_LO 32768
#define K3S_X_HI 65536
#define K3S_X_LO 98304
#define K3S_RAW  131072
#define K3_SMEM  196608

__device__ __forceinline__ void cvt_tile(const float* __restrict__ src,
                                         char* hi_base, char* lo_base, int tid) {
#pragma unroll
    for (int i = 0; i < 16; i++) {
        const int idx = tid + i * 256;
        const int row = idx >> 5;
        const int kb  = (idx & 31) << 3;
        const float4 x = *(const float4*)(src + idx * 4);
        __nv_bfloat162 h0 = __floats2bfloat162_rn(x.x, x.y);
        __nv_bfloat162 h1 = __floats2bfloat162_rn(x.z, x.w);
        float2 f0 = __bfloat1622float2(h0);
        float2 f1 = __bfloat1622float2(h1);
        __nv_bfloat162 l0 = __floats2bfloat162_rn(x.x - f0.x, x.y - f0.y);
        __nv_bfloat162 l1 = __floats2bfloat162_rn(x.z - f1.x, x.w - f1.y);
        const unsigned off = sw_off(row, kb);
        *(__nv_bfloat162*)(hi_base + off)     = h0;
        *(__nv_bfloat162*)(hi_base + off + 4) = h1;
        *(__nv_bfloat162*)(lo_base + off)     = l0;
        *(__nv_bfloat162*)(lo_base + off + 4) = l1;
    }
}

__global__ void __launch_bounds__(256, 1)
k3_out_mma(const float* __restrict__ X, float* __restrict__ out)
{
    extern __shared__ char smem[];
    const int tid  = threadIdx.x;
    const int lane = tid & 31;
    const int warp = tid >> 5;

    const int m0 = (warp & 1) * 64;
    const int n0 = (warp >> 1) * 32;
    const int qr = lane >> 2;
    const int qc = lane & 3;

    const char* xh = smem + K3S_X_HI;
    const char* xl = smem + K3S_X_LO;
    const char* wh = smem + K3S_W_HI;
    const char* wl = smem + K3S_W_LO;
    float* raw = (float*)(smem + K3S_RAW);

    // Prologue: cp.async first chunk's raw X (128 pts x 128 = 4096 f4)
    {
        const float* src = X + (size_t)blockIdx.x * 16384;
#pragma unroll
        for (int i = 0; i < 16; i++)
            cp16(raw + (tid + i * 256) * 4, src + (tid + i * 256) * 4);
        cp_commit();
    }

    int cur_b = -1;
    for (int chunk = blockIdx.x; chunk < NCHUNK3; chunk += NPART) {
        const int b = chunk >> 9;

        cp_wait_all();
        __syncthreads();   // raw ready; all prev MMA tile reads done

        if (b != cur_b) {
            cvt_tile(g_wqeff + b * 16384, smem + K3S_W_HI, smem + K3S_W_LO, tid);
            cur_b = b;
        }
        cvt_tile(raw, smem + K3S_X_HI, smem + K3S_X_LO, tid);
        __syncthreads();   // tiles visible; all raw reads done

        // prefetch next chunk (safe: after sync, no thread reads raw anymore)
        {
            const int nxt = chunk + NPART;
            if (nxt < NCHUNK3) {
                const float* src = X + (size_t)nxt * 16384;
#pragma unroll
                for (int i = 0; i < 16; i++)
                    cp16(raw + (tid + i * 256) * 4, src + (tid + i * 256) * 4);
                cp_commit();
            }
        }

        float c[4][4][4];
#pragma unroll
        for (int mi = 0; mi < 4; mi++)
#pragma unroll
            for (int nj = 0; nj < 4; nj++)
#pragma unroll
                for (int z = 0; z < 4; z++) c[mi][nj][z] = 0.f;

#pragma unroll
        for (int ks = 0; ks < 8; ks++) {
            const int kb = ks * 32 + qc * 4;
            unsigned ah[4][4], al[4][4], bh[4][2], bl[4][2];
#pragma unroll
            for (int mi = 0; mi < 4; mi++) {
                const int r = m0 + mi * 16 + qr;
                const unsigned o0 = sw_off(r,     kb);
                const unsigned o1 = sw_off(r + 8, kb);
                const unsigned o2 = sw_off(r,     kb + 16);
                const unsigned o3 = sw_off(r + 8, kb + 16);
                ah[mi][0] = *(const unsigned*)(xh + o0);
                ah[mi][1] = *(const unsigned*)(xh + o1);
                ah[mi][2] = *(const unsigned*)(xh + o2);
                ah[mi][3] = *(const unsigned*)(xh + o3);
                al[mi][0] = *(const unsigned*)(xl + o0);
                al[mi][1] = *(const unsigned*)(xl + o1);
                al[mi][2] = *(const unsigned*)(xl + o2);
                al[mi][3] = *(const unsigned*)(xl + o3);
            }
#pragma unroll
            for (int nj = 0; nj < 4; nj++) {
                const int n = n0 + nj * 8 + qr;
                const unsigned o0 = sw_off(n, kb);
                const unsigned o1 = sw_off(n, kb + 16);
                bh[nj][0] = *(const unsigned*)(wh + o0);
                bh[nj][1] = *(const unsigned*)(wh + o1);
                bl[nj][0] = *(const unsigned*)(wl + o0);
                bl[nj][1] = *(const unsigned*)(wl + o1);
            }

#pragma unroll
            for (int mi = 0; mi < 4; mi++)
#pragma unroll
                for (int nj = 0; nj < 4; nj++)
                    mma_bf16(c[mi][nj], ah[mi][0], ah[mi][1], ah[mi][2], ah[mi][3],
                             bh[nj][0], bh[nj][1]);
#pragma unroll
            for (int mi = 0; mi < 4; mi++)
#pragma unroll
                for (int nj = 0; nj < 4; nj++)
                    mma_bf16(c[mi][nj], ah[mi][0], ah[mi][1], ah[mi][2], ah[mi][3],
                             bl[nj][0], bl[nj][1]);
#pragma unroll
            for (int mi = 0; mi < 4; mi++)
#pragma unroll
                for (int nj = 0; nj < 4; nj++)
                    mma_bf16(c[mi][nj], al[mi][0], al[mi][1], al[mi][2], al[mi][3],
                             bh[nj][0], bh[nj][1]);
        }

        float* obase = out + (size_t)chunk * 16384;
#pragma unroll
        for (int mi = 0; mi < 4; mi++) {
            const int r = m0 + mi * 16 + qr;
#pragma unroll
            for (int nj = 0; nj < 4; nj++) {
                const int col = n0 + nj * 8 + qc * 2;
                *(float2*)(obase + r * 128 + col) =
                    make_float2(c[mi][nj][0], c[mi][nj][1]);
                *(float2*)(obase + (r + 8) * 128 + col) =
                    make_float2(c[mi][nj][2], c[mi][nj][3]);
            }
        }
    }
}

// ============================================================================
extern "C" void kernel_launch(void* const* d_in, const int* in_sizes, int n_in,
                              void* d_out, int out_size)
{
    (void)in_sizes; (void)n_in; (void)out_size;
    const float* X     = (const float*)d_in[0];
    const float* Wq    = (const float*)d_in[1];
    const float* Wk    = (const float*)d_in[2];
    const float* Wv    = (const float*)d_in[3];
    const float* gamma = (const float*)d_in[4];
    const float* beta  = (const float*)d_in[5];
    float* out = (float*)d_out;

    cudaFuncSetAttribute(k1_kv_mma, cudaFuncAttributeMaxDynamicSharedMemorySize,
                         K1_SMEM);    // 224 KB
    cudaFuncSetAttribute(k3_out_mma, cudaFuncAttributeMaxDynamicSharedMemorySize,
                         K3_SMEM);    // 192 KB

    k1_kv_mma<<<NPART, 256, K1_SMEM>>>(X, Wk, Wv, gamma, beta);
    k2a_reduce<<<64, 256>>>();
    k2b_fold<<<256, 256>>>(Wq);
    k3_out_mma<<<NPART, 256, K3_SMEM>>>(X, out);
}

// round 7
// speedup vs baseline: 1.8752x; 1.0011x over previous
#include <cuda_runtime.h>
#include <cuda_bf16.h>

// Problem constants
#define NPART    148     // persistent CTAs (one per SM)
#define NCHUNK1  4096    // K1: chunks of 64 points  (262144/64);  b = chunk>>10
#define NCHUNK3  2048    // K3: chunks of 128 points (262144/128); b = chunk>>9

// Deterministic scratch (no cudaMalloc allowed)
__device__ float g_part[4 * NPART * 4096];   // per-CTA partial kv  [b][cta][h*1024+d*32+e]
__device__ float g_kv[4 * 4096];             // reduced kv          [b][h*1024+d*32+e]
__device__ float g_wqeff[4 * 16384];         // folded weights      [b][n*128 + c]  (n = e*4+h)

// ---- packed f32x2 helpers ----
__device__ __forceinline__ unsigned long long dup2(float x) {
    unsigned long long r;
    asm("mov.b64 %0, {%1, %1};" : "=l"(r) : "f"(x));
    return r;
}
__device__ __forceinline__ unsigned long long fma2(unsigned long long a,
                                                   unsigned long long b,
                                                   unsigned long long c) {
    unsigned long long d;
    asm("fma.rn.f32x2 %0, %1, %2, %3;" : "=l"(d) : "l"(a), "l"(b), "l"(c));
    return d;
}
__device__ __forceinline__ float2 unpk(unsigned long long a) {
    float2 f;
    asm("mov.b64 {%0, %1}, %2;" : "=f"(f.x), "=f"(f.y) : "l"(a));
    return f;
}

// ---- cp.async helpers ----
__device__ __forceinline__ void cp16(void* smem_dst, const float* gsrc) {
    unsigned s = (unsigned)__cvta_generic_to_shared(smem_dst);
    asm volatile("cp.async.cg.shared.global [%0], [%1], 16;" :: "r"(s), "l"(gsrc));
}
__device__ __forceinline__ void cp_commit() {
    asm volatile("cp.async.commit_group;");
}
__device__ __forceinline__ void cp_wait_all() {
    asm volatile("cp.async.wait_group 0;");
}

// ---- shared mma.sync infrastructure ----
// bf16 tile [rows][256 bytes], XOR-swizzled at 16B granularity.
__device__ __forceinline__ unsigned sw_off(int row, int kbyte) {
    return (unsigned)((row << 8) + (kbyte ^ ((row & 7) << 4)));
}
// fp32 staging [rows][1024 bytes], XOR-swizzled at 16B granularity.
__device__ __forceinline__ unsigned skv_off(int row, int colb) {
    return (unsigned)((row << 10) + (colb ^ ((row & 7) << 4)));
}

__device__ __forceinline__ void mma_bf16(float* c,
                                         unsigned a0, unsigned a1, unsigned a2, unsigned a3,
                                         unsigned b0, unsigned b1) {
    asm volatile(
        "mma.sync.aligned.m16n8k16.row.col.f32.bf16.bf16.f32 "
        "{%0,%1,%2,%3}, {%4,%5,%6,%7}, {%8,%9}, {%0,%1,%2,%3};"
        : "+f"(c[0]), "+f"(c[1]), "+f"(c[2]), "+f"(c[3])
        : "r"(a0), "r"(a1), "r"(a2), "r"(a3), "r"(b0), "r"(b1));
}

// ============================================================================
// Kernel 1 (mma.sync, 512 threads): X@(Wk|Wv) bf16x3 -> LN -> outer partials
// 64-point chunks, register-resident X prefetch.
// smem: WT_hi 64K | WT_lo 64K | Xhi 16K | Xlo 16K | sKV 64K = 224 KB
// ============================================================================
#define K1_WT_HI 0
#define K1_WT_LO 65536
#define K1_X_HI  131072
#define K1_X_LO  147456
#define K1_KV    163840
#define K1_SMEM  229376

__global__ void __launch_bounds__(512, 1)
k1_kv_mma(const float* __restrict__ X,
          const float* __restrict__ Wk, const float* __restrict__ Wv,
          const float* __restrict__ gamma, const float* __restrict__ beta)
{
    extern __shared__ char smem[];
    char* wth = smem + K1_WT_HI;
    char* wtl = smem + K1_WT_LO;
    char* xh  = smem + K1_X_HI;
    char* xl  = smem + K1_X_LO;
    char* skv = smem + K1_KV;

    const int tid  = threadIdx.x;
    const int lane = tid & 31;
    const int warp = tid >> 5;   // 16 warps
    const int qr = lane >> 2;    // 0..7
    const int qc = lane & 3;     // 0..3

    // ---- One-time: transpose + bf16-split Wk|Wv into WT tiles (rows = out ch) ----
    for (int idx = tid; idx < 4096; idx += 512) {
        const int c  = idx >> 5;
        const int n4 = (idx & 31) << 2;
        const float4 wk = ((const float4*)Wk)[idx];
        const float4 wv = ((const float4*)Wv)[idx];
#pragma unroll
        for (int j = 0; j < 4; j++) {
            const float vk = (&wk.x)[j];
            const float vv = (&wv.x)[j];
            __nv_bfloat16 hk = __float2bfloat16(vk);
            __nv_bfloat16 hv = __float2bfloat16(vv);
            __nv_bfloat16 lk = __float2bfloat16(vk - __bfloat162float(hk));
            __nv_bfloat16 lv = __float2bfloat16(vv - __bfloat162float(hv));
            const unsigned ok = sw_off(n4 + j,       c * 2);
            const unsigned ov = sw_off(128 + n4 + j, c * 2);
            *(__nv_bfloat16*)(wth + ok) = hk;
            *(__nv_bfloat16*)(wtl + ok) = lk;
            *(__nv_bfloat16*)(wth + ov) = hv;
            *(__nv_bfloat16*)(wtl + ov) = lv;
        }
    }

    const float4 g4  = ((const float4*)gamma)[lane];
    const float4 be4 = ((const float4*)beta)[lane];

    // Outer-product entry assignment: 4096 entries / 512 threads = 8 (4d x 2e)
    const int hh   = tid >> 7;             // head 0..3
    const int idx2 = tid & 127;
    const int d0 = (idx2 >> 4) << 2;       // 0,4,...,28
    const int e0 = (idx2 & 15) << 1;       // 0,2,...,30
    const unsigned kcb = (unsigned)((hh * 32 + d0) * 4);         // k byte-col
    const unsigned vcb = (unsigned)(512 + (hh * 32 + e0) * 4);   // v byte-col (8B aligned)

    unsigned long long acc[4];             // [d] : one e-pair each
#pragma unroll
    for (int i = 0; i < 4; i++) acc[i] = 0ull;

    // MMA warp tile: 32 rows x 32 cols
    const int m0 = (warp & 1) * 32;
    const int n0 = (warp >> 1) * 32;

    // Prologue: LDG first chunk's raw X into registers (2048 f4 / 512 thr = 4)
    float4 xr[4];
    {
        const float4* src = (const float4*)X + (size_t)blockIdx.x * 2048;
#pragma unroll
        for (int i = 0; i < 4; i++) xr[i] = src[tid + i * 512];
    }

    int cur_b = -1;
    for (int chunk = blockIdx.x; chunk < NCHUNK1; chunk += NPART) {
        const int b = chunk >> 10;
        if (b != cur_b) {
            if (cur_b >= 0) {
                float* dst = g_part + ((size_t)cur_b * NPART + blockIdx.x) * 4096
                           + hh * 1024 + d0 * 32 + e0;
#pragma unroll
                for (int i = 0; i < 4; i++) {
                    *(float2*)(dst + i * 32) = unpk(acc[i]);
                    acc[i] = 0ull;
                }
            }
            cur_b = b;
        }

        // ---- convert register-resident raw X -> Xhi/Xlo swizzled bf16 tiles ----
#pragma unroll
        for (int i = 0; i < 4; i++) {
            const int idx = tid + i * 512;
            const int row = idx >> 5;          // 0..63
            const int kb  = (idx & 31) << 3;
            const float4 x = xr[i];
            __nv_bfloat162 h0 = __floats2bfloat162_rn(x.x, x.y);
            __nv_bfloat162 h1 = __floats2bfloat162_rn(x.z, x.w);
            float2 f0 = __bfloat1622float2(h0);
            float2 f1 = __bfloat1622float2(h1);
            __nv_bfloat162 l0 = __floats2bfloat162_rn(x.x - f0.x, x.y - f0.y);
            __nv_bfloat162 l1 = __floats2bfloat162_rn(x.z - f1.x, x.w - f1.y);
            const unsigned off = sw_off(row, kb);
            *(__nv_bfloat162*)(xh + off)     = h0;
            *(__nv_bfloat162*)(xh + off + 4) = h1;
            *(__nv_bfloat162*)(xl + off)     = l0;
            *(__nv_bfloat162*)(xl + off + 4) = l1;
        }

        // ---- prefetch next chunk's raw X into registers ----
        {
            const int nxt = chunk + NPART;
            if (nxt < NCHUNK1) {
                const float4* src = (const float4*)X + (size_t)nxt * 2048;
#pragma unroll
                for (int i = 0; i < 4; i++) xr[i] = src[tid + i * 512];
            }
        }
        __syncthreads();   // tiles visible; prev outer's sKV reads done

        // ---- MMA: kv_raw[64pt][256ch] = X @ (Wk|Wv)  (bf16x3) ----
        float c[2][4][4];
#pragma unroll
        for (int mi = 0; mi < 2; mi++)
#pragma unroll
            for (int nj = 0; nj < 4; nj++)
#pragma unroll
                for (int z = 0; z < 4; z++) c[mi][nj][z] = 0.f;

#pragma unroll
        for (int ks = 0; ks < 8; ks++) {
            const int kb = ks * 32 + qc * 4;
            unsigned ah[2][4], al[2][4], bh[4][2], bl[4][2];
#pragma unroll
            for (int mi = 0; mi < 2; mi++) {
                const int r = m0 + mi * 16 + qr;
                const unsigned o0 = sw_off(r,     kb);
                const unsigned o1 = sw_off(r + 8, kb);
                const unsigned o2 = sw_off(r,     kb + 16);
                const unsigned o3 = sw_off(r + 8, kb + 16);
                ah[mi][0] = *(const unsigned*)(xh + o0);
                ah[mi][1] = *(const unsigned*)(xh + o1);
                ah[mi][2] = *(const unsigned*)(xh + o2);
                ah[mi][3] = *(const unsigned*)(xh + o3);
                al[mi][0] = *(const unsigned*)(xl + o0);
                al[mi][1] = *(const unsigned*)(xl + o1);
                al[mi][2] = *(const unsigned*)(xl + o2);
                al[mi][3] = *(const unsigned*)(xl + o3);
            }
#pragma unroll
            for (int nj = 0; nj < 4; nj++) {
                const int n = n0 + nj * 8 + qr;
                const unsigned o0 = sw_off(n, kb);
                const unsigned o1 = sw_off(n, kb + 16);
                bh[nj][0] = *(const unsigned*)(wth + o0);
                bh[nj][1] = *(const unsigned*)(wth + o1);
                bl[nj][0] = *(const unsigned*)(wtl + o0);
                bl[nj][1] = *(const unsigned*)(wtl + o1);
            }
#pragma unroll
            for (int mi = 0; mi < 2; mi++)
#pragma unroll
                for (int nj = 0; nj < 4; nj++) {
                    mma_bf16(c[mi][nj], ah[mi][0], ah[mi][1], ah[mi][2], ah[mi][3],
                             bh[nj][0], bh[nj][1]);
                    mma_bf16(c[mi][nj], ah[mi][0], ah[mi][1], ah[mi][2], ah[mi][3],
                             bl[nj][0], bl[nj][1]);
                    mma_bf16(c[mi][nj], al[mi][0], al[mi][1], al[mi][2], al[mi][3],
                             bh[nj][0], bh[nj][1]);
                }
        }

        // ---- store raw k|v to swizzled fp32 staging ----
#pragma unroll
        for (int mi = 0; mi < 2; mi++) {
            const int r = m0 + mi * 16 + qr;
#pragma unroll
            for (int nj = 0; nj < 4; nj++) {
                const int colb = (n0 + nj * 8 + qc * 2) * 4;
                *(float2*)(skv + skv_off(r,     colb)) = make_float2(c[mi][nj][0], c[mi][nj][1]);
                *(float2*)(skv + skv_off(r + 8, colb)) = make_float2(c[mi][nj][2], c[mi][nj][3]);
            }
        }
        __syncthreads();

        // ---- LayerNorm in place (16 warps x 4 points) ----
#pragma unroll
        for (int p = 0; p < 4; p++) {
            const int pt = (warp << 2) + p;
            float4* kp = (float4*)(skv + skv_off(pt, lane * 16));
            float4* vp = (float4*)(skv + skv_off(pt, 512 + lane * 16));
            const float4 kk = *kp;
            const float4 vv = *vp;
            float sk = kk.x + kk.y + kk.z + kk.w;
            float qk = kk.x * kk.x + kk.y * kk.y + kk.z * kk.z + kk.w * kk.w;
            float sv = vv.x + vv.y + vv.z + vv.w;
            float qv = vv.x * vv.x + vv.y * vv.y + vv.z * vv.z + vv.w * vv.w;
#pragma unroll
            for (int off = 16; off; off >>= 1) {
                sk += __shfl_xor_sync(0xffffffffu, sk, off);
                qk += __shfl_xor_sync(0xffffffffu, qk, off);
                sv += __shfl_xor_sync(0xffffffffu, sv, off);
                qv += __shfl_xor_sync(0xffffffffu, qv, off);
            }
            const float muk = sk * (1.f / 128.f);
            const float rk  = rsqrtf(qk * (1.f / 128.f) - muk * muk + 1e-5f);
            const float muv = sv * (1.f / 128.f);
            const float rv  = rsqrtf(qv * (1.f / 128.f) - muv * muv + 1e-5f);
            *kp = make_float4((kk.x - muk) * rk * g4.x + be4.x,
                              (kk.y - muk) * rk * g4.y + be4.y,
                              (kk.z - muk) * rk * g4.z + be4.z,
                              (kk.w - muk) * rk * g4.w + be4.w);
            *vp = make_float4((vv.x - muv) * rv * g4.x + be4.x,
                              (vv.y - muv) * rv * g4.y + be4.y,
                              (vv.z - muv) * rv * g4.z + be4.z,
                              (vv.w - muv) * rv * g4.w + be4.w);
        }
        __syncthreads();

        // ---- outer-product accumulate over 64 points (4 fma2/pt/thread) ----
#pragma unroll 8
        for (int p = 0; p < 64; p++) {
            const float4 kk = *(const float4*)(skv + skv_off(p, kcb));
            const unsigned long long vv = *(const unsigned long long*)(skv + skv_off(p, vcb));
            acc[0] = fma2(vv, dup2(kk.x), acc[0]);
            acc[1] = fma2(vv, dup2(kk.y), acc[1]);
            acc[2] = fma2(vv, dup2(kk.z), acc[2]);
            acc[3] = fma2(vv, dup2(kk.w), acc[3]);
        }
    }

    if (cur_b >= 0) {
        float* dst = g_part + ((size_t)cur_b * NPART + blockIdx.x) * 4096
                   + hh * 1024 + d0 * 32 + e0;
#pragma unroll
        for (int i = 0; i < 4; i++)
            *(float2*)(dst + i * 32) = unpk(acc[i]);
    }
}

// ============================================================================
// Kernel 2a: reduce 148 per-CTA partials -> g_kv.
// ============================================================================
__global__ void k2a_reduce()
{
    const int gid = blockIdx.x * 256 + threadIdx.x;
    const int b = gid >> 12;
    const int e = gid & 4095;
    const float* src = g_part + (size_t)b * NPART * 4096 + e;
    float s = 0.f;
#pragma unroll 4
    for (int j = 0; j < NPART; j++) s += src[(size_t)j * 4096];
    g_kv[gid] = s;
}

// ============================================================================
// Kernel 2b: Wq_eff[b][n][c] = (1/N) * sum_d Wq[c][h*32+d] * kv[b][h][d][e]
// ============================================================================
__global__ void k2b_fold(const float* __restrict__ Wq)
{
    const int gid = blockIdx.x * 256 + threadIdx.x;   // 0..65535
    const int b  = gid >> 14;
    const int r  = gid & 16383;
    const int cp = r >> 7;
    const int co = r & 127;
    const int e  = co >> 2;
    const int h  = co & 3;
    const float* wq = Wq + cp * 128 + h * 32;
    const float* kv = g_kv + b * 4096 + h * 1024 + e;
    float s = 0.f;
#pragma unroll
    for (int d = 0; d < 32; d++) s += wq[d] * kv[d * 32];
    g_wqeff[b * 16384 + co * 128 + cp] = s * (1.f / 65536.f);
}

// ============================================================================
// Kernel 3 (mma.sync + cp.async, 512 threads): out = X @ Wq_eff[b]^T  (bf16x3)
// smem: Whi 32K | Wlo 32K | Xhi 32K | Xlo 32K | raw 64K = 192 KB
// ============================================================================
#define K3S_W_HI 0
#define K3S_W_LO 32768
#define K3S_X_HI 65536
#define K3S_X_LO 98304
#define K3S_RAW  131072
#define K3_SMEM  196608

__device__ __forceinline__ void cvt_tile512(const float* __restrict__ src,
                                            char* hi_base, char* lo_base, int tid) {
#pragma unroll
    for (int i = 0; i < 8; i++) {
        const int idx = tid + i * 512;
        const int row = idx >> 5;
        const int kb  = (idx & 31) << 3;
        const float4 x = *(const float4*)(src + idx * 4);
        __nv_bfloat162 h0 = __floats2bfloat162_rn(x.x, x.y);
        __nv_bfloat162 h1 = __floats2bfloat162_rn(x.z, x.w);
        float2 f0 = __bfloat1622float2(h0);
        float2 f1 = __bfloat1622float2(h1);
        __nv_bfloat162 l0 = __floats2bfloat162_rn(x.x - f0.x, x.y - f0.y);
        __nv_bfloat162 l1 = __floats2bfloat162_rn(x.z - f1.x, x.w - f1.y);
        const unsigned off = sw_off(row, kb);
        *(__nv_bfloat162*)(hi_base + off)     = h0;
        *(__nv_bfloat162*)(hi_base + off + 4) = h1;
        *(__nv_bfloat162*)(lo_base + off)     = l0;
        *(__nv_bfloat162*)(lo_base + off + 4) = l1;
    }
}

// Convert W (only 128 rows): first 256 threads active.
__device__ __forceinline__ void cvt_w512(const float* __restrict__ src,
                                         char* hi_base, char* lo_base, int tid) {
    if (tid < 256) {
#pragma unroll
        for (int i = 0; i < 16; i++) {
            const int idx = tid + i * 256;
            const int row = idx >> 5;
            const int kb  = (idx & 31) << 3;
            const float4 x = *(const float4*)(src + idx * 4);
            __nv_bfloat162 h0 = __floats2bfloat162_rn(x.x, x.y);
            __nv_bfloat162 h1 = __floats2bfloat162_rn(x.z, x.w);
            float2 f0 = __bfloat1622float2(h0);
            float2 f1 = __bfloat1622float2(h1);
            __nv_bfloat162 l0 = __floats2bfloat162_rn(x.x - f0.x, x.y - f0.y);
            __nv_bfloat162 l1 = __floats2bfloat162_rn(x.z - f1.x, x.w - f1.y);
            const unsigned off = sw_off(row, kb);
            *(__nv_bfloat162*)(hi_base + off)     = h0;
            *(__nv_bfloat162*)(hi_base + off + 4) = h1;
            *(__nv_bfloat162*)(lo_base + off)     = l0;
            *(__nv_bfloat162*)(lo_base + off + 4) = l1;
        }
    }
}

__global__ void __launch_bounds__(512, 1)
k3_out_mma(const float* __restrict__ X, float* __restrict__ out)
{
    extern __shared__ char smem[];
    const int tid  = threadIdx.x;
    const int lane = tid & 31;
    const int warp = tid >> 5;   // 16 warps

    // 4x4 grid of 32x32 warp tiles over 128x128 output
    const int m0 = (warp & 3) * 32;
    const int n0 = (warp >> 2) * 32;
    const int qr = lane >> 2;
    const int qc = lane & 3;

    const char* xh = smem + K3S_X_HI;
    const char* xl = smem + K3S_X_LO;
    const char* wh = smem + K3S_W_HI;
    const char* wl = smem + K3S_W_LO;
    float* raw = (float*)(smem + K3S_RAW);

    // Prologue: cp.async first chunk's raw X (4096 f4 / 512 thr = 8)
    {
        const float* src = X + (size_t)blockIdx.x * 16384;
#pragma unroll
        for (int i = 0; i < 8; i++)
            cp16(raw + (tid + i * 512) * 4, src + (tid + i * 512) * 4);
        cp_commit();
    }

    int cur_b = -1;
    for (int chunk = blockIdx.x; chunk < NCHUNK3; chunk += NPART) {
        const int b = chunk >> 9;

        cp_wait_all();
        __syncthreads();   // raw ready; all prev MMA tile reads done

        if (b != cur_b) {
            cvt_w512(g_wqeff + b * 16384, smem + K3S_W_HI, smem + K3S_W_LO, tid);
            cur_b = b;
        }
        cvt_tile512(raw, smem + K3S_X_HI, smem + K3S_X_LO, tid);
        __syncthreads();   // tiles visible; all raw reads done

        // prefetch next chunk (safe: after sync, no thread reads raw anymore)
        {
            const int nxt = chunk + NPART;
            if (nxt < NCHUNK3) {
                const float* src = X + (size_t)nxt * 16384;
#pragma unroll
                for (int i = 0; i < 8; i++)
                    cp16(raw + (tid + i * 512) * 4, src + (tid + i * 512) * 4);
                cp_commit();
            }
        }

        float c[2][4][4];
#pragma unroll
        for (int mi = 0; mi < 2; mi++)
#pragma unroll
            for (int nj = 0; nj < 4; nj++)
#pragma unroll
                for (int z = 0; z < 4; z++) c[mi][nj][z] = 0.f;

#pragma unroll
        for (int ks = 0; ks < 8; ks++) {
            const int kb = ks * 32 + qc * 4;
            unsigned ah[2][4], al[2][4], bh[4][2], bl[4][2];
#pragma unroll
            for (int mi = 0; mi < 2; mi++) {
                const int r = m0 + mi * 16 + qr;
                const unsigned o0 = sw_off(r,     kb);
                const unsigned o1 = sw_off(r + 8, kb);
                const unsigned o2 = sw_off(r,     kb + 16);
                const unsigned o3 = sw_off(r + 8, kb + 16);
                ah[mi][0] = *(const unsigned*)(xh + o0);
                ah[mi][1] = *(const unsigned*)(xh + o1);
                ah[mi][2] = *(const unsigned*)(xh + o2);
                ah[mi][3] = *(const unsigned*)(xh + o3);
                al[mi][0] = *(const unsigned*)(xl + o0);
                al[mi][1] = *(const unsigned*)(xl + o1);
                al[mi][2] = *(const unsigned*)(xl + o2);
                al[mi][3] = *(const unsigned*)(xl + o3);
            }
#pragma unroll
            for (int nj = 0; nj < 4; nj++) {
                const int n = n0 + nj * 8 + qr;
                const unsigned o0 = sw_off(n, kb);
                const unsigned o1 = sw_off(n, kb + 16);
                bh[nj][0] = *(const unsigned*)(wh + o0);
                bh[nj][1] = *(const unsigned*)(wh + o1);
                bl[nj][0] = *(const unsigned*)(wl + o0);
                bl[nj][1] = *(const unsigned*)(wl + o1);
            }

#pragma unroll
            for (int mi = 0; mi < 2; mi++)
#pragma unroll
                for (int nj = 0; nj < 4; nj++) {
                    mma_bf16(c[mi][nj], ah[mi][0], ah[mi][1], ah[mi][2], ah[mi][3],
                             bh[nj][0], bh[nj][1]);
                    mma_bf16(c[mi][nj], ah[mi][0], ah[mi][1], ah[mi][2], ah[mi][3],
                             bl[nj][0], bl[nj][1]);
                    mma_bf16(c[mi][nj], al[mi][0], al[mi][1], al[mi][2], al[mi][3],
                             bh[nj][0], bh[nj][1]);
                }
        }

        float* obase = out + (size_t)chunk * 16384;
#pragma unroll
        for (int mi = 0; mi < 2; mi++) {
            const int r = m0 + mi * 16 + qr;
#pragma unroll
            for (int nj = 0; nj < 4; nj++) {
                const int col = n0 + nj * 8 + qc * 2;
                *(float2*)(obase + r * 128 + col) =
                    make_float2(c[mi][nj][0], c[mi][nj][1]);
                *(float2*)(obase + (r + 8) * 128 + col) =
                    make_float2(c[mi][nj][2], c[mi][nj][3]);
            }
        }
    }
}

// ============================================================================
extern "C" void kernel_launch(void* const* d_in, const int* in_sizes, int n_in,
                              void* d_out, int out_size)
{
    (void)in_sizes; (void)n_in; (void)out_size;
    const float* X     = (const float*)d_in[0];
    const float* Wq    = (const float*)d_in[1];
    const float* Wk    = (const float*)d_in[2];
    const float* Wv    = (const float*)d_in[3];
    const float* gamma = (const float*)d_in[4];
    const float* beta  = (const float*)d_in[5];
    float* out = (float*)d_out;

    cudaFuncSetAttribute(k1_kv_mma, cudaFuncAttributeMaxDynamicSharedMemorySize,
                         K1_SMEM);    // 224 KB
    cudaFuncSetAttribute(k3_out_mma, cudaFuncAttributeMaxDynamicSharedMemorySize,
                         K3_SMEM);    // 192 KB

    k1_kv_mma<<<NPART, 512, K1_SMEM>>>(X, Wk, Wv, gamma, beta);
    k2a_reduce<<<64, 256>>>();
    k2b_fold<<<256, 256>>>(Wq);
    k3_out_mma<<<NPART, 512, K3_SMEM>>>(X, out);
}

// round 8
// speedup vs baseline: 2.1454x; 1.1441x over previous
#include <cuda_runtime.h>
#include <cuda_bf16.h>

// Problem constants
#define NPART    148     // persistent CTAs (one per SM)
#define NCHUNK1  4096    // K1: chunks of 64 points  (262144/64);  b = chunk>>10
#define NCHUNK3  2048    // K3: chunks of 128 points (262144/128); b = chunk>>9

// Deterministic scratch (no cudaMalloc allowed)
__device__ float g_part[4 * NPART * 4096];   // per-CTA partial kv  [b][cta][h*1024+d*32+e]
__device__ float g_kv[4 * 4096];             // reduced kv          [b][h*1024+d*32+e]
__device__ float g_wqeff[4 * 16384];         // folded weights      [b][n*128 + c]  (n = e*4+h)

// ---- packed f32x2 helpers ----
__device__ __forceinline__ unsigned long long dup2(float x) {
    unsigned long long r;
    asm("mov.b64 %0, {%1, %1};" : "=l"(r) : "f"(x));
    return r;
}
__device__ __forceinline__ unsigned long long fma2(unsigned long long a,
                                                   unsigned long long b,
                                                   unsigned long long c) {
    unsigned long long d;
    asm("fma.rn.f32x2 %0, %1, %2, %3;" : "=l"(d) : "l"(a), "l"(b), "l"(c));
    return d;
}
__device__ __forceinline__ float2 unpk(unsigned long long a) {
    float2 f;
    asm("mov.b64 {%0, %1}, %2;" : "=f"(f.x), "=f"(f.y) : "l"(a));
    return f;
}

// ---- cp.async helpers ----
__device__ __forceinline__ void cp16(void* smem_dst, const float* gsrc) {
    unsigned s = (unsigned)__cvta_generic_to_shared(smem_dst);
    asm volatile("cp.async.cg.shared.global [%0], [%1], 16;" :: "r"(s), "l"(gsrc));
}
__device__ __forceinline__ void cp_commit() {
    asm volatile("cp.async.commit_group;");
}
__device__ __forceinline__ void cp_wait_all() {
    asm volatile("cp.async.wait_group 0;");
}

// ---- shared mma.sync infrastructure ----
// bf16 tile [rows][256 bytes], XOR-swizzled at 16B granularity.
__device__ __forceinline__ unsigned sw_off(int row, int kbyte) {
    return (unsigned)((row << 8) + (kbyte ^ ((row & 7) << 4)));
}
// fp32 staging [rows][1024 bytes], XOR-swizzled at 16B granularity.
__device__ __forceinline__ unsigned skv_off(int row, int colb) {
    return (unsigned)((row << 10) + (colb ^ ((row & 7) << 4)));
}

__device__ __forceinline__ void mma_bf16(float* c,
                                         unsigned a0, unsigned a1, unsigned a2, unsigned a3,
                                         unsigned b0, unsigned b1) {
    asm volatile(
        "mma.sync.aligned.m16n8k16.row.col.f32.bf16.bf16.f32 "
        "{%0,%1,%2,%3}, {%4,%5,%6,%7}, {%8,%9}, {%0,%1,%2,%3};"
        : "+f"(c[0]), "+f"(c[1]), "+f"(c[2]), "+f"(c[3])
        : "r"(a0), "r"(a1), "r"(a2), "r"(a3), "r"(b0), "r"(b1));
}

__device__ __forceinline__ void ldsm4(unsigned* r, unsigned a) {
    asm volatile("ldmatrix.sync.aligned.m8n8.x4.shared.b16 {%0,%1,%2,%3}, [%4];"
                 : "=r"(r[0]), "=r"(r[1]), "=r"(r[2]), "=r"(r[3]) : "r"(a));
}

// ============================================================================
// Kernel 1 (mma.sync + ldmatrix, 512 threads): X@(Wk|Wv) bf16x3 -> LN (stats
// from registers) -> outer-product partials.
// smem: WT_hi 64K | WT_lo 64K | Xhi 16K | Xlo 16K | sKV 64K (part arrays
// aliased on its first 4K) | stats 1K | gb 1K = 226 KB
// ============================================================================
#define K1_WT_HI 0
#define K1_WT_LO 65536
#define K1_X_HI  131072
#define K1_X_LO  147456
#define K1_KV    163840
#define K1_PK    163840            // part_k: 64 rows x 4 x float2 (2 KB, alias)
#define K1_PV    165888            // part_v: 2 KB (alias)
#define K1_STATS 229376            // 64 x float4
#define K1_GB    230400            // 128 x float2 (gamma, beta)
#define K1_SMEM  231424

__global__ void __launch_bounds__(512, 1)
k1_kv_mma(const float* __restrict__ X,
          const float* __restrict__ Wk, const float* __restrict__ Wv,
          const float* __restrict__ gamma, const float* __restrict__ beta)
{
    extern __shared__ char smem[];
    char* wth = smem + K1_WT_HI;
    char* wtl = smem + K1_WT_LO;
    char* xh  = smem + K1_X_HI;
    char* xl  = smem + K1_X_LO;
    char* skv = smem + K1_KV;
    float2* partk = (float2*)(smem + K1_PK);
    float2* partv = (float2*)(smem + K1_PV);
    float4* stats = (float4*)(smem + K1_STATS);
    float2* gb    = (float2*)(smem + K1_GB);

    const unsigned xh_u  = (unsigned)__cvta_generic_to_shared(xh);
    const unsigned wth_u = (unsigned)__cvta_generic_to_shared(wth);

    const int tid  = threadIdx.x;
    const int lane = tid & 31;
    const int warp = tid >> 5;   // 16 warps
    const int qr = lane >> 2;    // 0..7
    const int qc = lane & 3;     // 0..3

    // ---- One-time: transpose + bf16-split Wk|Wv into WT tiles ----
    for (int idx = tid; idx < 4096; idx += 512) {
        const int c  = idx >> 5;
        const int n4 = (idx & 31) << 2;
        const float4 wk = ((const float4*)Wk)[idx];
        const float4 wv = ((const float4*)Wv)[idx];
#pragma unroll
        for (int j = 0; j < 4; j++) {
            const float vk = (&wk.x)[j];
            const float vv = (&wv.x)[j];
            __nv_bfloat16 hk = __float2bfloat16(vk);
            __nv_bfloat16 hv = __float2bfloat16(vv);
            __nv_bfloat16 lk = __float2bfloat16(vk - __bfloat162float(hk));
            __nv_bfloat16 lv = __float2bfloat16(vv - __bfloat162float(hv));
            const unsigned ok = sw_off(n4 + j,       c * 2);
            const unsigned ov = sw_off(128 + n4 + j, c * 2);
            *(__nv_bfloat16*)(wth + ok) = hk;
            *(__nv_bfloat16*)(wtl + ok) = lk;
            *(__nv_bfloat16*)(wth + ov) = hv;
            *(__nv_bfloat16*)(wtl + ov) = lv;
        }
    }
    // gamma/beta LUT
    for (int i = tid; i < 128; i += 512)
        gb[i] = make_float2(gamma[i], beta[i]);

    // Outer-product entry assignment: 4096 entries / 512 threads = 8 (4d x 2e)
    const int hh   = tid >> 7;
    const int idx2 = tid & 127;
    const int d0 = (idx2 >> 4) << 2;
    const int e0 = (idx2 & 15) << 1;
    const unsigned kcb = (unsigned)((hh * 32 + d0) * 4);
    const unsigned vcb = (unsigned)(512 + (hh * 32 + e0) * 4);

    unsigned long long acc[4];
#pragma unroll
    for (int i = 0; i < 4; i++) acc[i] = 0ull;

    // MMA warp tile: 32 rows x 32 cols
    const int m0 = (warp & 1) * 32;
    const int n0 = (warp >> 1) * 32;
    const int kwarp = (warp < 8);          // this warp's cols are k (else v)
    const int nw = kwarp ? (warp >> 1) : ((warp >> 1) - 4);

    // ldmatrix address precompute
    const int laneK = lane & 16;
    const int bKoff = (lane & 8) << 1;
    unsigned aBase[2], aSw[2], bBase[2], bSw[2];
#pragma unroll
    for (int mi = 0; mi < 2; mi++) {
        const int row = m0 + mi * 16 + (lane & 15);
        aSw[mi] = (unsigned)((row & 7) << 4);
        aBase[mi] = xh_u + row * 256;
    }
#pragma unroll
    for (int p = 0; p < 2; p++) {
        const int row = n0 + p * 16 + ((lane >> 1) & 8) + (lane & 7);
        bSw[p] = (unsigned)((row & 7) << 4);
        bBase[p] = wth_u + row * 256;
    }

    // Prologue: LDG first chunk's raw X into registers
    float4 xr[4];
    {
        const float4* src = (const float4*)X + (size_t)blockIdx.x * 2048;
#pragma unroll
        for (int i = 0; i < 4; i++) xr[i] = src[tid + i * 512];
    }

    int cur_b = -1;
    for (int chunk = blockIdx.x; chunk < NCHUNK1; chunk += NPART) {
        const int b = chunk >> 10;
        if (b != cur_b) {
            if (cur_b >= 0) {
                float* dst = g_part + ((size_t)cur_b * NPART + blockIdx.x) * 4096
                           + hh * 1024 + d0 * 32 + e0;
#pragma unroll
                for (int i = 0; i < 4; i++) {
                    *(float2*)(dst + i * 32) = unpk(acc[i]);
                    acc[i] = 0ull;
                }
            }
            cur_b = b;
        }

        // ---- convert raw X regs -> Xhi/Xlo swizzled bf16 tiles ----
#pragma unroll
        for (int i = 0; i < 4; i++) {
            const int idx = tid + i * 512;
            const int row = idx >> 5;
            const int kb  = (idx & 31) << 3;
            const float4 x = xr[i];
            __nv_bfloat162 h0 = __floats2bfloat162_rn(x.x, x.y);
            __nv_bfloat162 h1 = __floats2bfloat162_rn(x.z, x.w);
            float2 f0 = __bfloat1622float2(h0);
            float2 f1 = __bfloat1622float2(h1);
            __nv_bfloat162 l0 = __floats2bfloat162_rn(x.x - f0.x, x.y - f0.y);
            __nv_bfloat162 l1 = __floats2bfloat162_rn(x.z - f1.x, x.w - f1.y);
            const unsigned off = sw_off(row, kb);
            *(__nv_bfloat162*)(xh + off)     = h0;
            *(__nv_bfloat162*)(xh + off + 4) = h1;
            *(__nv_bfloat162*)(xl + off)     = l0;
            *(__nv_bfloat162*)(xl + off + 4) = l1;
        }

        // ---- prefetch next chunk's raw X ----
        {
            const int nxt = chunk + NPART;
            if (nxt < NCHUNK1) {
                const float4* src = (const float4*)X + (size_t)nxt * 2048;
#pragma unroll
                for (int i = 0; i < 4; i++) xr[i] = src[tid + i * 512];
            }
        }
        __syncthreads();   // tiles visible; prev outer's sKV reads done

        // ---- MMA via ldmatrix: kv_raw[64pt][256ch] = X @ (Wk|Wv)  (bf16x3) ----
        float c[2][4][4];
#pragma unroll
        for (int mi = 0; mi < 2; mi++)
#pragma unroll
            for (int nj = 0; nj < 4; nj++)
#pragma unroll
                for (int z = 0; z < 4; z++) c[mi][nj][z] = 0.f;

#pragma unroll
        for (int ks = 0; ks < 8; ks++) {
            const int kb = ks * 32;
            unsigned ah[2][4], al[2][4], bh[4][2], bl[4][2];
#pragma unroll
            for (int mi = 0; mi < 2; mi++) {
                const unsigned off = (unsigned)(kb + laneK) ^ aSw[mi];
                ldsm4(ah[mi], aBase[mi] + off);
                ldsm4(al[mi], aBase[mi] + 16384u + off);
            }
#pragma unroll
            for (int p = 0; p < 2; p++) {
                const unsigned off = (unsigned)(kb + bKoff) ^ bSw[p];
                unsigned t[4];
                ldsm4(t, bBase[p] + off);
                bh[2 * p][0] = t[0]; bh[2 * p][1] = t[1];
                bh[2 * p + 1][0] = t[2]; bh[2 * p + 1][1] = t[3];
                ldsm4(t, bBase[p] + 65536u + off);
                bl[2 * p][0] = t[0]; bl[2 * p][1] = t[1];
                bl[2 * p + 1][0] = t[2]; bl[2 * p + 1][1] = t[3];
            }
#pragma unroll
            for (int mi = 0; mi < 2; mi++)
#pragma unroll
                for (int nj = 0; nj < 4; nj++) {
                    mma_bf16(c[mi][nj], ah[mi][0], ah[mi][1], ah[mi][2], ah[mi][3],
                             bh[nj][0], bh[nj][1]);
                    mma_bf16(c[mi][nj], ah[mi][0], ah[mi][1], ah[mi][2], ah[mi][3],
                             bl[nj][0], bl[nj][1]);
                    mma_bf16(c[mi][nj], al[mi][0], al[mi][1], al[mi][2], al[mi][3],
                             bh[nj][0], bh[nj][1]);
                }
        }

        // ---- per-warp partial LN stats from registers ----
#pragma unroll
        for (int mi = 0; mi < 2; mi++) {
#pragma unroll
            for (int half = 0; half < 2; half++) {
                float s = 0.f, q = 0.f;
#pragma unroll
                for (int nj = 0; nj < 4; nj++) {
                    const float v0 = c[mi][nj][half * 2];
                    const float v1 = c[mi][nj][half * 2 + 1];
                    s += v0 + v1;
                    q += v0 * v0 + v1 * v1;
                }
                s += __shfl_xor_sync(0xffffffffu, s, 1);
                q += __shfl_xor_sync(0xffffffffu, q, 1);
                s += __shfl_xor_sync(0xffffffffu, s, 2);
                q += __shfl_xor_sync(0xffffffffu, q, 2);
                if (qc == 0) {
                    const int row = m0 + mi * 16 + half * 8 + qr;
                    (kwarp ? partk : partv)[row * 4 + nw] = make_float2(s, q);
                }
            }
        }
        __syncthreads();

        // ---- stats: 64 threads, one per point ----
        if (tid < 64) {
            const float4 k0 = ((const float4*)partk)[tid * 2];
            const float4 k1 = ((const float4*)partk)[tid * 2 + 1];
            const float4 v0 = ((const float4*)partv)[tid * 2];
            const float4 v1 = ((const float4*)partv)[tid * 2 + 1];
            const float sk = k0.x + k0.z + k1.x + k1.z;
            const float qk = k0.y + k0.w + k1.y + k1.w;
            const float sv = v0.x + v0.z + v1.x + v1.z;
            const float qv = v0.y + v0.w + v1.y + v1.w;
            const float muk = sk * (1.f / 128.f);
            const float rk  = rsqrtf(qk * (1.f / 128.f) - muk * muk + 1e-5f);
            const float muv = sv * (1.f / 128.f);
            const float rv  = rsqrtf(qv * (1.f / 128.f) - muv * muv + 1e-5f);
            stats[tid] = make_float4(muk, rk, muv, rv);
        }
        __syncthreads();

        // ---- normalize c registers, store kn/vn to sKV ----
        {
            float gv[8], bv[8];
#pragma unroll
            for (int nj = 0; nj < 4; nj++)
#pragma unroll
                for (int zz = 0; zz < 2; zz++) {
                    const int ch = (n0 + nj * 8 + qc * 2 + zz) & 127;
                    const float2 gbv = gb[ch];
                    gv[nj * 2 + zz] = gbv.x;
                    bv[nj * 2 + zz] = gbv.y;
                }
#pragma unroll
            for (int mi = 0; mi < 2; mi++) {
#pragma unroll
                for (int half = 0; half < 2; half++) {
                    const int row = m0 + mi * 16 + half * 8 + qr;
                    const float4 st = stats[row];
                    const float mu = kwarp ? st.x : st.z;
                    const float rr = kwarp ? st.y : st.w;
                    const float mm = -mu * rr;
#pragma unroll
                    for (int nj = 0; nj < 4; nj++) {
#pragma unroll
                        for (int zz = 0; zz < 2; zz++) {
                            float& v = c[mi][nj][half * 2 + zz];
                            v = fmaf(fmaf(v, rr, mm), gv[nj * 2 + zz], bv[nj * 2 + zz]);
                        }
                    }
                }
            }
            // store
#pragma unroll
            for (int mi = 0; mi < 2; mi++) {
                const int r = m0 + mi * 16 + qr;
#pragma unroll
                for (int nj = 0; nj < 4; nj++) {
                    const int colb = (n0 + nj * 8 + qc * 2) * 4;
                    *(float2*)(skv + skv_off(r,     colb)) = make_float2(c[mi][nj][0], c[mi][nj][1]);
                    *(float2*)(skv + skv_off(r + 8, colb)) = make_float2(c[mi][nj][2], c[mi][nj][3]);
                }
            }
        }
        __syncthreads();

        // ---- outer-product accumulate over 64 points ----
#pragma unroll 8
        for (int p = 0; p < 64; p++) {
            const float4 kk = *(const float4*)(skv + skv_off(p, kcb));
            const unsigned long long vv = *(const unsigned long long*)(skv + skv_off(p, vcb));
            acc[0] = fma2(vv, dup2(kk.x), acc[0]);
            acc[1] = fma2(vv, dup2(kk.y), acc[1]);
            acc[2] = fma2(vv, dup2(kk.z), acc[2]);
            acc[3] = fma2(vv, dup2(kk.w), acc[3]);
        }
    }

    if (cur_b >= 0) {
        float* dst = g_part + ((size_t)cur_b * NPART + blockIdx.x) * 4096
                   + hh * 1024 + d0 * 32 + e0;
#pragma unroll
        for (int i = 0; i < 4; i++)
            *(float2*)(dst + i * 32) = unpk(acc[i]);
    }
}

// ============================================================================
// Kernel 2a: reduce 148 per-CTA partials -> g_kv.
// ============================================================================
__global__ void k2a_reduce()
{
    const int gid = blockIdx.x * 256 + threadIdx.x;
    const int b = gid >> 12;
    const int e = gid & 4095;
    const float* src = g_part + (size_t)b * NPART * 4096 + e;
    float s = 0.f;
#pragma unroll 4
    for (int j = 0; j < NPART; j++) s += src[(size_t)j * 4096];
    g_kv[gid] = s;
}

// ============================================================================
// Kernel 2b: Wq_eff[b][n][c] = (1/N) * sum_d Wq[c][h*32+d] * kv[b][h][d][e]
// ============================================================================
__global__ void k2b_fold(const float* __restrict__ Wq)
{
    const int gid = blockIdx.x * 256 + threadIdx.x;
    const int b  = gid >> 14;
    const int r  = gid & 16383;
    const int cp = r >> 7;
    const int co = r & 127;
    const int e  = co >> 2;
    const int h  = co & 3;
    const float* wq = Wq + cp * 128 + h * 32;
    const float* kv = g_kv + b * 4096 + h * 1024 + e;
    float s = 0.f;
#pragma unroll
    for (int d = 0; d < 32; d++) s += wq[d] * kv[d * 32];
    g_wqeff[b * 16384 + co * 128 + cp] = s * (1.f / 65536.f);
}

// ============================================================================
// Kernel 3 (mma.sync + ldmatrix + cp.async, 512 threads): out = X @ Wq_eff^T
// smem: Whi 32K | Wlo 32K | Xhi 32K | Xlo 32K | raw 64K = 192 KB
// ============================================================================
#define K3S_W_HI 0
#define K3S_W_LO 32768
#define K3S_X_HI 65536
#define K3S_X_LO 98304
#define K3S_RAW  131072
#define K3_SMEM  196608

__device__ __forceinline__ void cvt_tile512(const float* __restrict__ src,
                                            char* hi_base, char* lo_base, int tid) {
#pragma unroll
    for (int i = 0; i < 8; i++) {
        const int idx = tid + i * 512;
        const int row = idx >> 5;
        const int kb  = (idx & 31) << 3;
        const float4 x = *(const float4*)(src + idx * 4);
        __nv_bfloat162 h0 = __floats2bfloat162_rn(x.x, x.y);
        __nv_bfloat162 h1 = __floats2bfloat162_rn(x.z, x.w);
        float2 f0 = __bfloat1622float2(h0);
        float2 f1 = __bfloat1622float2(h1);
        __nv_bfloat162 l0 = __floats2bfloat162_rn(x.x - f0.x, x.y - f0.y);
        __nv_bfloat162 l1 = __floats2bfloat162_rn(x.z - f1.x, x.w - f1.y);
        const unsigned off = sw_off(row, kb);
        *(__nv_bfloat162*)(hi_base + off)     = h0;
        *(__nv_bfloat162*)(hi_base + off + 4) = h1;
        *(__nv_bfloat162*)(lo_base + off)     = l0;
        *(__nv_bfloat162*)(lo_base + off + 4) = l1;
    }
}

__device__ __forceinline__ void cvt_w512(const float* __restrict__ src,
                                         char* hi_base, char* lo_base, int tid) {
    if (tid < 256) {
#pragma unroll
        for (int i = 0; i < 16; i++) {
            const int idx = tid + i * 256;
            const int row = idx >> 5;
            const int kb  = (idx & 31) << 3;
            const float4 x = *(const float4*)(src + idx * 4);
            __nv_bfloat162 h0 = __floats2bfloat162_rn(x.x, x.y);
            __nv_bfloat162 h1 = __floats2bfloat162_rn(x.z, x.w);
            float2 f0 = __bfloat1622float2(h0);
            float2 f1 = __bfloat1622float2(h1);
            __nv_bfloat162 l0 = __floats2bfloat162_rn(x.x - f0.x, x.y - f0.y);
            __nv_bfloat162 l1 = __floats2bfloat162_rn(x.z - f1.x, x.w - f1.y);
            const unsigned off = sw_off(row, kb);
            *(__nv_bfloat162*)(hi_base + off)     = h0;
            *(__nv_bfloat162*)(hi_base + off + 4) = h1;
            *(__nv_bfloat162*)(lo_base + off)     = l0;
            *(__nv_bfloat162*)(lo_base + off + 4) = l1;
        }
    }
}

__global__ void __launch_bounds__(512, 1)
k3_out_mma(const float* __restrict__ X, float* __restrict__ out)
{
    extern __shared__ char smem[];
    const int tid  = threadIdx.x;
    const int lane = tid & 31;
    const int warp = tid >> 5;   // 16 warps

    const int m0 = (warp & 3) * 32;
    const int n0 = (warp >> 2) * 32;
    const int qr = lane >> 2;
    const int qc = lane & 3;

    const char* xh = smem + K3S_X_HI;
    const char* wh = smem + K3S_W_HI;
    float* raw = (float*)(smem + K3S_RAW);

    const unsigned xh_u = (unsigned)__cvta_generic_to_shared(xh);
    const unsigned wh_u = (unsigned)__cvta_generic_to_shared(wh);

    // ldmatrix address precompute
    const int laneK = lane & 16;
    const int bKoff = (lane & 8) << 1;
    unsigned aBase[2], aSw[2], bBase[2], bSw[2];
#pragma unroll
    for (int mi = 0; mi < 2; mi++) {
        const int row = m0 + mi * 16 + (lane & 15);
        aSw[mi] = (unsigned)((row & 7) << 4);
        aBase[mi] = xh_u + row * 256;
    }
#pragma unroll
    for (int p = 0; p < 2; p++) {
        const int row = n0 + p * 16 + ((lane >> 1) & 8) + (lane & 7);
        bSw[p] = (unsigned)((row & 7) << 4);
        bBase[p] = wh_u + row * 256;
    }

    // Prologue: cp.async first chunk's raw X
    {
        const float* src = X + (size_t)blockIdx.x * 16384;
#pragma unroll
        for (int i = 0; i < 8; i++)
            cp16(raw + (tid + i * 512) * 4, src + (tid + i * 512) * 4);
        cp_commit();
    }

    int cur_b = -1;
    for (int chunk = blockIdx.x; chunk < NCHUNK3; chunk += NPART) {
        const int b = chunk >> 9;

        cp_wait_all();
        __syncthreads();   // raw ready; all prev MMA tile reads done

        if (b != cur_b) {
            cvt_w512(g_wqeff + b * 16384, smem + K3S_W_HI, smem + K3S_W_LO, tid);
            cur_b = b;
        }
        cvt_tile512(raw, smem + K3S_X_HI, smem + K3S_X_LO, tid);
        __syncthreads();   // tiles visible; all raw reads done

        // prefetch next chunk
        {
            const int nxt = chunk + NPART;
            if (nxt < NCHUNK3) {
                const float* src = X + (size_t)nxt * 16384;
#pragma unroll
                for (int i = 0; i < 8; i++)
                    cp16(raw + (tid + i * 512) * 4, src + (tid + i * 512) * 4);
                cp_commit();
            }
        }

        float c[2][4][4];
#pragma unroll
        for (int mi = 0; mi < 2; mi++)
#pragma unroll
            for (int nj = 0; nj < 4; nj++)
#pragma unroll
                for (int z = 0; z < 4; z++) c[mi][nj][z] = 0.f;

#pragma unroll
        for (int ks = 0; ks < 8; ks++) {
            const int kb = ks * 32;
            unsigned ah[2][4], al[2][4], bh[4][2], bl[4][2];
#pragma unroll
            for (int mi = 0; mi < 2; mi++) {
                const unsigned off = (unsigned)(kb + laneK) ^ aSw[mi];
                ldsm4(ah[mi], aBase[mi] + off);
                ldsm4(al[mi], aBase[mi] + 32768u + off);
            }
#pragma unroll
            for (int p = 0; p < 2; p++) {
                const unsigned off = (unsigned)(kb + bKoff) ^ bSw[p];
                unsigned t[4];
                ldsm4(t, bBase[p] + off);
                bh[2 * p][0] = t[0]; bh[2 * p][1] = t[1];
                bh[2 * p + 1][0] = t[2]; bh[2 * p + 1][1] = t[3];
                ldsm4(t, bBase[p] + 32768u + off);
                bl[2 * p][0] = t[0]; bl[2 * p][1] = t[1];
                bl[2 * p + 1][0] = t[2]; bl[2 * p + 1][1] = t[3];
            }
#pragma unroll
            for (int mi = 0; mi < 2; mi++)
#pragma unroll
                for (int nj = 0; nj < 4; nj++) {
                    mma_bf16(c[mi][nj], ah[mi][0], ah[mi][1], ah[mi][2], ah[mi][3],
                             bh[nj][0], bh[nj][1]);
                    mma_bf16(c[mi][nj], ah[mi][0], ah[mi][1], ah[mi][2], ah[mi][3],
                             bl[nj][0], bl[nj][1]);
                    mma_bf16(c[mi][nj], al[mi][0], al[mi][1], al[mi][2], al[mi][3],
                             bh[nj][0], bh[nj][1]);
                }
        }

        float* obase = out + (size_t)chunk * 16384;
#pragma unroll
        for (int mi = 0; mi < 2; mi++) {
            const int r = m0 + mi * 16 + qr;
#pragma unroll
            for (int nj = 0; nj < 4; nj++) {
                const int col = n0 + nj * 8 + qc * 2;
                *(float2*)(obase + r * 128 + col) =
                    make_float2(c[mi][nj][0], c[mi][nj][1]);
                *(float2*)(obase + (r + 8) * 128 + col) =
                    make_float2(c[mi][nj][2], c[mi][nj][3]);
            }
        }
    }
}

// ============================================================================
extern "C" void kernel_launch(void* const* d_in, const int* in_sizes, int n_in,
                              void* d_out, int out_size)
{
    (void)in_sizes; (void)n_in; (void)out_size;
    const float* X     = (const float*)d_in[0];
    const float* Wq    = (const float*)d_in[1];
    const float* Wk    = (const float*)d_in[2];
    const float* Wv    = (const float*)d_in[3];
    const float* gamma = (const float*)d_in[4];
    const float* beta  = (const float*)d_in[5];
    float* out = (float*)d_out;

    cudaFuncSetAttribute(k1_kv_mma, cudaFuncAttributeMaxDynamicSharedMemorySize,
                         K1_SMEM);    // 226 KB
    cudaFuncSetAttribute(k3_out_mma, cudaFuncAttributeMaxDynamicSharedMemorySize,
                         K3_SMEM);    // 192 KB

    k1_kv_mma<<<NPART, 512, K1_SMEM>>>(X, Wk, Wv, gamma, beta);
    k2a_reduce<<<64, 256>>>();
    k2b_fold<<<256, 256>>>(Wq);
    k3_out_mma<<<NPART, 512, K3_SMEM>>>(X, out);
}